// round 1
// baseline (speedup 1.0000x reference)
#include <cuda_runtime.h>
#include <math.h>

#define BATCH 4
#define SEQ   2048
#define DM    1024
#define DFF   4096
#define NHEAD 16
#define HD    64
#define NROWS (BATCH*SEQ)   /* 8192 */

// ---------------- scratch (device globals; no allocation allowed) ----------
__device__ float g_xn  [(size_t)NROWS * DM];        // 32 MB  (LN output, reused)
__device__ float g_qkv [(size_t)NROWS * 3 * DM];    // 96 MB
__device__ float g_attn[(size_t)NROWS * DM];        // 32 MB
__device__ float g_res1[(size_t)NROWS * DM];        // 32 MB
__device__ float g_ff  [(size_t)NROWS * DFF];       // 128 MB

// ---------------- LayerNorm ------------------------------------------------
__global__ __launch_bounds__(256) void ln_kernel(
    const float* __restrict__ x, const float* __restrict__ scale,
    const float* __restrict__ bias, float* __restrict__ out)
{
    int row = blockIdx.x;
    const float4* xr = (const float4*)(x + (size_t)row * DM);
    float4 v = xr[threadIdx.x];                 // 256 thr * 4 = 1024 elems
    float s  = v.x + v.y + v.z + v.w;
    float ss = v.x*v.x + v.y*v.y + v.z*v.z + v.w*v.w;
    #pragma unroll
    for (int o = 16; o > 0; o >>= 1) {
        s  += __shfl_xor_sync(0xffffffffu, s,  o);
        ss += __shfl_xor_sync(0xffffffffu, ss, o);
    }
    __shared__ float smS[8], smSS[8];
    __shared__ float sMean, sRstd;
    int w = threadIdx.x >> 5, lane = threadIdx.x & 31;
    if (lane == 0) { smS[w] = s; smSS[w] = ss; }
    __syncthreads();
    if (threadIdx.x == 0) {
        float S = 0.f, SS = 0.f;
        #pragma unroll
        for (int i = 0; i < 8; i++) { S += smS[i]; SS += smSS[i]; }
        float mean = S * (1.0f / DM);
        float var  = SS * (1.0f / DM) - mean * mean;
        sMean = mean;
        sRstd = rsqrtf(var + 1e-6f);
    }
    __syncthreads();
    float mean = sMean, rstd = sRstd;
    int c = threadIdx.x * 4;
    float4 sc = *(const float4*)(scale + c);
    float4 bi = *(const float4*)(bias  + c);
    float4 o;
    o.x = (v.x - mean) * rstd * sc.x + bi.x;
    o.y = (v.y - mean) * rstd * sc.y + bi.y;
    o.z = (v.z - mean) * rstd * sc.z + bi.z;
    o.w = (v.w - mean) * rstd * sc.w + bi.w;
    ((float4*)(out + (size_t)row * DM))[threadIdx.x] = o;
}

// ---------------- GELU (tanh approx == jax.nn.gelu default) ----------------
__device__ __forceinline__ float gelu_f(float x)
{
    float x3 = x * x * x;
    return 0.5f * x * (1.0f + tanhf(0.7978845608028654f * (x + 0.044715f * x3)));
}

// ---------------- SGEMM: C = A[M,K] @ B[K,N] + bias (+res / +gelu) ---------
// 128x128 tile, BK=8, 256 threads, 8x8 per thread.
// epi: 0 = bias only, 1 = bias + residual, 2 = gelu(bias+acc)
__global__ __launch_bounds__(256) void gemm_kernel(
    const float* __restrict__ A, const float* __restrict__ B,
    const float* __restrict__ bias, const float* __restrict__ R,
    float* __restrict__ C, int M, int N, int K, int epi)
{
    __shared__ float As[8][128];
    __shared__ float Bs[8][128];
    int t  = threadIdx.x;
    int m0 = blockIdx.y * 128, n0 = blockIdx.x * 128;
    int ty = t >> 4, tx = t & 15;

    float acc[8][8];
    #pragma unroll
    for (int i = 0; i < 8; i++)
        #pragma unroll
        for (int j = 0; j < 8; j++) acc[i][j] = 0.f;

    int arow = t >> 1,  acol = (t & 1) * 4;
    int brow = t >> 5,  bcol = (t & 31) * 4;
    const float* Aptr = A + (size_t)(m0 + arow) * K + acol;
    const float* Bptr = B + (size_t)brow * N + n0 + bcol;

    for (int k0 = 0; k0 < K; k0 += 8) {
        float4 a4 = *(const float4*)(Aptr + k0);
        float4 b4 = *(const float4*)(Bptr + (size_t)k0 * N);
        As[acol + 0][arow] = a4.x;
        As[acol + 1][arow] = a4.y;
        As[acol + 2][arow] = a4.z;
        As[acol + 3][arow] = a4.w;
        *(float4*)&Bs[brow][bcol] = b4;
        __syncthreads();
        #pragma unroll
        for (int kk = 0; kk < 8; kk++) {
            float a[8], b[8];
            *(float4*)(a)     = *(float4*)&As[kk][ty * 8];
            *(float4*)(a + 4) = *(float4*)&As[kk][ty * 8 + 4];
            *(float4*)(b)     = *(float4*)&Bs[kk][tx * 8];
            *(float4*)(b + 4) = *(float4*)&Bs[kk][tx * 8 + 4];
            #pragma unroll
            for (int i = 0; i < 8; i++)
                #pragma unroll
                for (int j = 0; j < 8; j++)
                    acc[i][j] = fmaf(a[i], b[j], acc[i][j]);
        }
        __syncthreads();
    }

    int rowb = m0 + ty * 8, colb = n0 + tx * 8;
    #pragma unroll
    for (int i = 0; i < 8; i++) {
        float*       Crow = C + (size_t)(rowb + i) * N + colb;
        const float* Rrow = R ? (R + (size_t)(rowb + i) * N + colb) : (const float*)0;
        #pragma unroll
        for (int j = 0; j < 8; j++) {
            float c = acc[i][j] + bias[colb + j];
            if (epi == 1)      c += Rrow[j];
            else if (epi == 2) c  = gelu_f(c);
            Crow[j] = c;
        }
    }
}

// ---------------- Flash-attention (fp32, causal, online softmax) -----------
// grid: (SEQ/64, BATCH*NHEAD); block 256.  BQ = BK = 64, HD = 64.
#define ATTN_SMEM_FLOATS (3 * 64 * 65 + 64 * 64 + 3 * 64)
__global__ __launch_bounds__(256) void attn_kernel()
{
    extern __shared__ float sm[];
    float* Qt   = sm;                    // [64 d][65] transposed, pre-scaled
    float* Kt   = Qt + 64 * 65;          // [64 d][65] transposed
    float* Vs   = Kt + 64 * 65;          // [64 k][64 d]
    float* Ss   = Vs + 64 * 64;          // [64 q][65 k]
    float* rowM = Ss + 64 * 65;
    float* rowL = rowM + 64;
    float* rowS = rowL + 64;

    int t     = threadIdx.x;
    int qtile = blockIdx.x;
    int bh    = blockIdx.y;
    int b     = bh >> 4, h = bh & 15;
    size_t baseBH = (size_t)b * SEQ * (3 * DM) + (size_t)h * HD;
    int q0 = qtile * 64;
    int ty = t >> 4, tx = t & 15;

    // load Q tile transposed + scaled by 1/sqrt(64)
    for (int i = t; i < 64 * 16; i += 256) {
        int r = i >> 4, c4 = (i & 15) * 4;
        float4 v = *(const float4*)&g_qkv[baseBH + (size_t)(q0 + r) * (3 * DM) + c4];
        Qt[(c4 + 0) * 65 + r] = v.x * 0.125f;
        Qt[(c4 + 1) * 65 + r] = v.y * 0.125f;
        Qt[(c4 + 2) * 65 + r] = v.z * 0.125f;
        Qt[(c4 + 3) * 65 + r] = v.w * 0.125f;
    }
    if (t < 64) { rowM[t] = -1e30f; rowL[t] = 0.f; }

    float acc[4][4];
    #pragma unroll
    for (int i = 0; i < 4; i++)
        #pragma unroll
        for (int j = 0; j < 4; j++) acc[i][j] = 0.f;

    for (int j0t = 0; j0t <= qtile; ++j0t) {
        int k0 = j0t * 64;
        // load K (transposed) and V tiles
        for (int i = t; i < 64 * 16; i += 256) {
            int r = i >> 4, c4 = (i & 15) * 4;
            size_t base = baseBH + (size_t)(k0 + r) * (3 * DM);
            float4 kv = *(const float4*)&g_qkv[base + DM + c4];
            Kt[(c4 + 0) * 65 + r] = kv.x;
            Kt[(c4 + 1) * 65 + r] = kv.y;
            Kt[(c4 + 2) * 65 + r] = kv.z;
            Kt[(c4 + 3) * 65 + r] = kv.w;
            float4 vv = *(const float4*)&g_qkv[base + 2 * DM + c4];
            *(float4*)&Vs[r * 64 + c4] = vv;
        }
        __syncthreads();

        // S = Q K^T  (4x4 per thread)
        float s[4][4];
        #pragma unroll
        for (int i = 0; i < 4; i++)
            #pragma unroll
            for (int j = 0; j < 4; j++) s[i][j] = 0.f;
        #pragma unroll 8
        for (int d = 0; d < 64; d++) {
            float a0 = Qt[d * 65 + ty * 4 + 0];
            float a1 = Qt[d * 65 + ty * 4 + 1];
            float a2 = Qt[d * 65 + ty * 4 + 2];
            float a3 = Qt[d * 65 + ty * 4 + 3];
            float b0 = Kt[d * 65 + tx * 4 + 0];
            float b1 = Kt[d * 65 + tx * 4 + 1];
            float b2 = Kt[d * 65 + tx * 4 + 2];
            float b3 = Kt[d * 65 + tx * 4 + 3];
            s[0][0] = fmaf(a0, b0, s[0][0]); s[0][1] = fmaf(a0, b1, s[0][1]);
            s[0][2] = fmaf(a0, b2, s[0][2]); s[0][3] = fmaf(a0, b3, s[0][3]);
            s[1][0] = fmaf(a1, b0, s[1][0]); s[1][1] = fmaf(a1, b1, s[1][1]);
            s[1][2] = fmaf(a1, b2, s[1][2]); s[1][3] = fmaf(a1, b3, s[1][3]);
            s[2][0] = fmaf(a2, b0, s[2][0]); s[2][1] = fmaf(a2, b1, s[2][1]);
            s[2][2] = fmaf(a2, b2, s[2][2]); s[2][3] = fmaf(a2, b3, s[2][3]);
            s[3][0] = fmaf(a3, b0, s[3][0]); s[3][1] = fmaf(a3, b1, s[3][1]);
            s[3][2] = fmaf(a3, b2, s[3][2]); s[3][3] = fmaf(a3, b3, s[3][3]);
        }
        if (j0t == qtile) {                     // causal mask on diagonal tile
            #pragma unroll
            for (int i = 0; i < 4; i++)
                #pragma unroll
                for (int j = 0; j < 4; j++) {
                    int qi = q0 + ty * 4 + i, ki = k0 + tx * 4 + j;
                    if (ki > qi) s[i][j] = -1e30f;
                }
        }
        #pragma unroll
        for (int i = 0; i < 4; i++)
            #pragma unroll
            for (int j = 0; j < 4; j++)
                Ss[(ty * 4 + i) * 65 + tx * 4 + j] = s[i][j];
        __syncthreads();

        // online softmax per row (64 threads)
        if (t < 64) {
            float m_old = rowM[t], m = m_old;
            #pragma unroll 8
            for (int k = 0; k < 64; k++) m = fmaxf(m, Ss[t * 65 + k]);
            float scl = __expf(m_old - m);
            float l = rowL[t] * scl;
            #pragma unroll 8
            for (int k = 0; k < 64; k++) {
                float p = __expf(Ss[t * 65 + k] - m);
                Ss[t * 65 + k] = p;
                l += p;
            }
            rowM[t] = m; rowL[t] = l; rowS[t] = scl;
        }
        __syncthreads();

        // rescale acc + accumulate P @ V
        float sci[4];
        #pragma unroll
        for (int i = 0; i < 4; i++) sci[i] = rowS[ty * 4 + i];
        #pragma unroll
        for (int i = 0; i < 4; i++)
            #pragma unroll
            for (int j = 0; j < 4; j++) acc[i][j] *= sci[i];
        #pragma unroll 8
        for (int k = 0; k < 64; k++) {
            float p0 = Ss[(ty * 4 + 0) * 65 + k];
            float p1 = Ss[(ty * 4 + 1) * 65 + k];
            float p2 = Ss[(ty * 4 + 2) * 65 + k];
            float p3 = Ss[(ty * 4 + 3) * 65 + k];
            float v0 = Vs[k * 64 + tx * 4 + 0];
            float v1 = Vs[k * 64 + tx * 4 + 1];
            float v2 = Vs[k * 64 + tx * 4 + 2];
            float v3 = Vs[k * 64 + tx * 4 + 3];
            acc[0][0] = fmaf(p0, v0, acc[0][0]); acc[0][1] = fmaf(p0, v1, acc[0][1]);
            acc[0][2] = fmaf(p0, v2, acc[0][2]); acc[0][3] = fmaf(p0, v3, acc[0][3]);
            acc[1][0] = fmaf(p1, v0, acc[1][0]); acc[1][1] = fmaf(p1, v1, acc[1][1]);
            acc[1][2] = fmaf(p1, v2, acc[1][2]); acc[1][3] = fmaf(p1, v3, acc[1][3]);
            acc[2][0] = fmaf(p2, v0, acc[2][0]); acc[2][1] = fmaf(p2, v1, acc[2][1]);
            acc[2][2] = fmaf(p2, v2, acc[2][2]); acc[2][3] = fmaf(p2, v3, acc[2][3]);
            acc[3][0] = fmaf(p3, v0, acc[3][0]); acc[3][1] = fmaf(p3, v1, acc[3][1]);
            acc[3][2] = fmaf(p3, v2, acc[3][2]); acc[3][3] = fmaf(p3, v3, acc[3][3]);
        }
        __syncthreads();
    }

    // write O = acc / l  into [B,S,D] head-concat layout
    float invl[4];
    #pragma unroll
    for (int i = 0; i < 4; i++) invl[i] = 1.0f / rowL[ty * 4 + i];
    #pragma unroll
    for (int i = 0; i < 4; i++) {
        int q = q0 + ty * 4 + i;
        float* orow = &g_attn[(size_t)(b * SEQ + q) * DM + h * HD + tx * 4];
        #pragma unroll
        for (int j = 0; j < 4; j++) orow[j] = acc[i][j] * invl[i];
    }
}

// ---------------- launch ---------------------------------------------------
extern "C" void kernel_launch(void* const* d_in, const int* in_sizes, int n_in,
                              void* d_out, int out_size)
{
    (void)in_sizes; (void)n_in; (void)out_size;
    const float* x     = (const float*)d_in[0];
    const float* w_qkv = (const float*)d_in[1];
    const float* b_qkv = (const float*)d_in[2];
    const float* w_out = (const float*)d_in[3];
    const float* b_out = (const float*)d_in[4];
    const float* w_fc1 = (const float*)d_in[5];
    const float* b_fc1 = (const float*)d_in[6];
    const float* w_fc2 = (const float*)d_in[7];
    const float* b_fc2 = (const float*)d_in[8];
    const float* ln1s  = (const float*)d_in[9];
    const float* ln1b  = (const float*)d_in[10];
    const float* ln2s  = (const float*)d_in[11];
    const float* ln2b  = (const float*)d_in[12];
    float* out = (float*)d_out;

    float *xn, *qkv, *attn, *res1, *ff;
    cudaGetSymbolAddress((void**)&xn,   g_xn);
    cudaGetSymbolAddress((void**)&qkv,  g_qkv);
    cudaGetSymbolAddress((void**)&attn, g_attn);
    cudaGetSymbolAddress((void**)&res1, g_res1);
    cudaGetSymbolAddress((void**)&ff,   g_ff);

    const int ATTN_SMEM_BYTES = ATTN_SMEM_FLOATS * 4;  // 67072
    cudaFuncSetAttribute(attn_kernel,
                         cudaFuncAttributeMaxDynamicSharedMemorySize,
                         ATTN_SMEM_BYTES);

    // 1. LN1
    ln_kernel<<<NROWS, 256>>>(x, ln1s, ln1b, xn);
    // 2. QKV projection
    gemm_kernel<<<dim3(3 * DM / 128, NROWS / 128), 256>>>(
        xn, w_qkv, b_qkv, (const float*)0, qkv, NROWS, 3 * DM, DM, 0);
    // 3. causal flash attention
    attn_kernel<<<dim3(SEQ / 64, BATCH * NHEAD), 256, ATTN_SMEM_BYTES>>>();
    // 4. out projection + residual(x)
    gemm_kernel<<<dim3(DM / 128, NROWS / 128), 256>>>(
        attn, w_out, b_out, x, res1, NROWS, DM, DM, 1);
    // 5. LN2
    ln_kernel<<<NROWS, 256>>>(res1, ln2s, ln2b, xn);
    // 6. FC1 + gelu
    gemm_kernel<<<dim3(DFF / 128, NROWS / 128), 256>>>(
        xn, w_fc1, b_fc1, (const float*)0, ff, NROWS, DFF, DM, 2);
    // 7. FC2 + residual(res1) -> out
    gemm_kernel<<<dim3(DM / 128, NROWS / 128), 256>>>(
        ff, w_fc2, b_fc2, res1, out, NROWS, DM, DFF, 1);
}

// round 2
// speedup vs baseline: 1.9489x; 1.9489x over previous
#include <cuda_runtime.h>
#include <math.h>

#define BATCH 4
#define SEQ   2048
#define DM    1024
#define DFF   4096
#define NHEAD 16
#define HD    64
#define NROWS (BATCH*SEQ)   /* 8192 */

// ---------------- scratch (device globals; no allocation allowed) ----------
__device__ float g_xn  [(size_t)NROWS * DM];        // 32 MB  (LN output, reused)
__device__ float g_qkv [(size_t)NROWS * 3 * DM];    // 96 MB
__device__ float g_attn[(size_t)NROWS * DM];        // 32 MB
__device__ float g_res1[(size_t)NROWS * DM];        // 32 MB
__device__ float g_ff  [(size_t)NROWS * DFF];       // 128 MB

// ---------------- LayerNorm ------------------------------------------------
__global__ __launch_bounds__(256) void ln_kernel(
    const float* __restrict__ x, const float* __restrict__ scale,
    const float* __restrict__ bias, float* __restrict__ out)
{
    int row = blockIdx.x;
    const float4* xr = (const float4*)(x + (size_t)row * DM);
    float4 v = xr[threadIdx.x];                 // 256 thr * 4 = 1024 elems
    float s  = v.x + v.y + v.z + v.w;
    float ss = v.x*v.x + v.y*v.y + v.z*v.z + v.w*v.w;
    #pragma unroll
    for (int o = 16; o > 0; o >>= 1) {
        s  += __shfl_xor_sync(0xffffffffu, s,  o);
        ss += __shfl_xor_sync(0xffffffffu, ss, o);
    }
    __shared__ float smS[8], smSS[8];
    __shared__ float sMean, sRstd;
    int w = threadIdx.x >> 5, lane = threadIdx.x & 31;
    if (lane == 0) { smS[w] = s; smSS[w] = ss; }
    __syncthreads();
    if (threadIdx.x == 0) {
        float S = 0.f, SS = 0.f;
        #pragma unroll
        for (int i = 0; i < 8; i++) { S += smS[i]; SS += smSS[i]; }
        float mean = S * (1.0f / DM);
        float var  = SS * (1.0f / DM) - mean * mean;
        sMean = mean;
        sRstd = rsqrtf(var + 1e-6f);
    }
    __syncthreads();
    float mean = sMean, rstd = sRstd;
    int c = threadIdx.x * 4;
    float4 sc = *(const float4*)(scale + c);
    float4 bi = *(const float4*)(bias  + c);
    float4 o;
    o.x = (v.x - mean) * rstd * sc.x + bi.x;
    o.y = (v.y - mean) * rstd * sc.y + bi.y;
    o.z = (v.z - mean) * rstd * sc.z + bi.z;
    o.w = (v.w - mean) * rstd * sc.w + bi.w;
    ((float4*)(out + (size_t)row * DM))[threadIdx.x] = o;
}

// ---------------- GELU (tanh approx == jax.nn.gelu default) ----------------
__device__ __forceinline__ float gelu_f(float x)
{
    float x3 = x * x * x;
    return 0.5f * x * (1.0f + tanhf(0.7978845608028654f * (x + 0.044715f * x3)));
}

// ---------------- TF32 tensor-core GEMM ------------------------------------
// C[M,N] = A[M,K] @ B[K,N] + bias (+ residual / gelu epilogues)
// Block tile 128x128, BK=16, 256 threads = 8 warps (2 warp-rows x 4 warp-cols),
// warp tile 64x32, mma.sync.m16n8k8.tf32, double-buffered smem.
// smem row stride 132 -> fragment loads are bank-conflict free (bank = 4k+m).
// epi: 0 = bias, 1 = bias + residual, 2 = gelu(bias + acc)

__device__ __forceinline__ unsigned f2tf32(float x)
{
    unsigned r;
    asm("cvt.rna.tf32.f32 %0, %1;" : "=r"(r) : "f"(x));
    return r;
}

#define SA 132

__global__ __launch_bounds__(256) void gemm_tf32_kernel(
    const float* __restrict__ A, const float* __restrict__ B,
    const float* __restrict__ bias, const float* __restrict__ R,
    float* __restrict__ C, int M, int N, int K, int epi)
{
    __shared__ unsigned As[2][16 * SA];
    __shared__ unsigned Bs[2][16 * SA];

    const int t    = threadIdx.x;
    const int m0   = blockIdx.y * 128, n0 = blockIdx.x * 128;
    const int w    = t >> 5, lane = t & 31;
    const int wr   = w >> 2, wc = w & 3;          // 2 x 4 warps
    const int wm   = wr * 64, wn = wc * 32;       // warp tile 64x32
    const int lr   = lane >> 2, lc = lane & 3;    // quad layout

    float c[4][4][4];
    #pragma unroll
    for (int mf = 0; mf < 4; mf++)
        #pragma unroll
        for (int nf = 0; nf < 4; nf++)
            #pragma unroll
            for (int i = 0; i < 4; i++) c[mf][nf][i] = 0.f;

    // global load addressing (each thread: 2 float4 of A, 2 float4 of B per tile)
    const int arow  = t >> 2;            // 0..63
    const int ac4   = (t & 3) << 2;      // k-offset 0,4,8,12
    const int brow  = t >> 5;            // 0..7
    const int bc4   = (t & 31) << 2;     // n-offset 0..124
    const float* Ap0 = A + (size_t)(m0 + arow)      * K + ac4;
    const float* Ap1 = A + (size_t)(m0 + 64 + arow) * K + ac4;
    const float* Bp0 = B + (size_t)brow       * N + n0 + bc4;
    const float* Bp1 = B + (size_t)(8 + brow) * N + n0 + bc4;

    float4 a4[2], b4[2];

    // prologue: tile k0 = 0
    a4[0] = *(const float4*)(Ap0);
    a4[1] = *(const float4*)(Ap1);
    b4[0] = *(const float4*)(Bp0);
    b4[1] = *(const float4*)(Bp1);
    {
        unsigned* as = As[0];
        as[(ac4 + 0) * SA + arow]      = f2tf32(a4[0].x);
        as[(ac4 + 1) * SA + arow]      = f2tf32(a4[0].y);
        as[(ac4 + 2) * SA + arow]      = f2tf32(a4[0].z);
        as[(ac4 + 3) * SA + arow]      = f2tf32(a4[0].w);
        as[(ac4 + 0) * SA + arow + 64] = f2tf32(a4[1].x);
        as[(ac4 + 1) * SA + arow + 64] = f2tf32(a4[1].y);
        as[(ac4 + 2) * SA + arow + 64] = f2tf32(a4[1].z);
        as[(ac4 + 3) * SA + arow + 64] = f2tf32(a4[1].w);
        unsigned* bs = Bs[0];
        bs[brow * SA + bc4 + 0]       = f2tf32(b4[0].x);
        bs[brow * SA + bc4 + 1]       = f2tf32(b4[0].y);
        bs[brow * SA + bc4 + 2]       = f2tf32(b4[0].z);
        bs[brow * SA + bc4 + 3]       = f2tf32(b4[0].w);
        bs[(brow + 8) * SA + bc4 + 0] = f2tf32(b4[1].x);
        bs[(brow + 8) * SA + bc4 + 1] = f2tf32(b4[1].y);
        bs[(brow + 8) * SA + bc4 + 2] = f2tf32(b4[1].z);
        bs[(brow + 8) * SA + bc4 + 3] = f2tf32(b4[1].w);
    }
    __syncthreads();

    int buf = 0;
    for (int k0 = 16; k0 <= K; k0 += 16) {
        bool more = (k0 < K);
        if (more) {
            a4[0] = *(const float4*)(Ap0 + k0);
            a4[1] = *(const float4*)(Ap1 + k0);
            b4[0] = *(const float4*)(Bp0 + (size_t)k0 * N);
            b4[1] = *(const float4*)(Bp1 + (size_t)k0 * N);
        }

        // compute current buffer
        const unsigned* as = As[buf];
        const unsigned* bs = Bs[buf];
        #pragma unroll
        for (int ks = 0; ks < 2; ks++) {
            const int kb = 8 * ks;
            unsigned af[4][4];
            #pragma unroll
            for (int mf = 0; mf < 4; mf++) {
                int mrow = wm + mf * 16 + lr;
                af[mf][0] = as[(kb + lc) * SA + mrow];
                af[mf][1] = as[(kb + lc) * SA + mrow + 8];
                af[mf][2] = as[(kb + lc + 4) * SA + mrow];
                af[mf][3] = as[(kb + lc + 4) * SA + mrow + 8];
            }
            unsigned bf[4][2];
            #pragma unroll
            for (int nf = 0; nf < 4; nf++) {
                int ncol = wn + nf * 8 + lr;
                bf[nf][0] = bs[(kb + lc) * SA + ncol];
                bf[nf][1] = bs[(kb + lc + 4) * SA + ncol];
            }
            #pragma unroll
            for (int mf = 0; mf < 4; mf++)
                #pragma unroll
                for (int nf = 0; nf < 4; nf++) {
                    asm volatile(
                        "mma.sync.aligned.m16n8k8.row.col.f32.tf32.tf32.f32 "
                        "{%0,%1,%2,%3}, {%4,%5,%6,%7}, {%8,%9}, {%0,%1,%2,%3};\n"
                        : "+f"(c[mf][nf][0]), "+f"(c[mf][nf][1]),
                          "+f"(c[mf][nf][2]), "+f"(c[mf][nf][3])
                        : "r"(af[mf][0]), "r"(af[mf][1]),
                          "r"(af[mf][2]), "r"(af[mf][3]),
                          "r"(bf[nf][0]), "r"(bf[nf][1]));
                }
        }

        if (more) {
            unsigned* asn = As[buf ^ 1];
            asn[(ac4 + 0) * SA + arow]      = f2tf32(a4[0].x);
            asn[(ac4 + 1) * SA + arow]      = f2tf32(a4[0].y);
            asn[(ac4 + 2) * SA + arow]      = f2tf32(a4[0].z);
            asn[(ac4 + 3) * SA + arow]      = f2tf32(a4[0].w);
            asn[(ac4 + 0) * SA + arow + 64] = f2tf32(a4[1].x);
            asn[(ac4 + 1) * SA + arow + 64] = f2tf32(a4[1].y);
            asn[(ac4 + 2) * SA + arow + 64] = f2tf32(a4[1].z);
            asn[(ac4 + 3) * SA + arow + 64] = f2tf32(a4[1].w);
            unsigned* bsn = Bs[buf ^ 1];
            bsn[brow * SA + bc4 + 0]       = f2tf32(b4[0].x);
            bsn[brow * SA + bc4 + 1]       = f2tf32(b4[0].y);
            bsn[brow * SA + bc4 + 2]       = f2tf32(b4[0].z);
            bsn[brow * SA + bc4 + 3]       = f2tf32(b4[0].w);
            bsn[(brow + 8) * SA + bc4 + 0] = f2tf32(b4[1].x);
            bsn[(brow + 8) * SA + bc4 + 1] = f2tf32(b4[1].y);
            bsn[(brow + 8) * SA + bc4 + 2] = f2tf32(b4[1].z);
            bsn[(brow + 8) * SA + bc4 + 3] = f2tf32(b4[1].w);
            __syncthreads();
            buf ^= 1;
        }
    }

    // -------- epilogue --------
    #pragma unroll
    for (int mf = 0; mf < 4; mf++) {
        #pragma unroll
        for (int nf = 0; nf < 4; nf++) {
            int row = m0 + wm + mf * 16 + lr;
            int col = n0 + wn + nf * 8 + lc * 2;
            float b0 = bias[col], b1 = bias[col + 1];
            float v0 = c[mf][nf][0] + b0;
            float v1 = c[mf][nf][1] + b1;
            float v2 = c[mf][nf][2] + b0;
            float v3 = c[mf][nf][3] + b1;
            if (epi == 1) {
                const float* r0 = R + (size_t)row * N + col;
                const float* r1 = R + (size_t)(row + 8) * N + col;
                v0 += r0[0]; v1 += r0[1];
                v2 += r1[0]; v3 += r1[1];
            } else if (epi == 2) {
                v0 = gelu_f(v0); v1 = gelu_f(v1);
                v2 = gelu_f(v2); v3 = gelu_f(v3);
            }
            float2 p0 = make_float2(v0, v1);
            float2 p1 = make_float2(v2, v3);
            *(float2*)(C + (size_t)row * N + col)       = p0;
            *(float2*)(C + (size_t)(row + 8) * N + col) = p1;
        }
    }
}

// ---------------- Flash-attention (fp32, causal, online softmax) -----------
// grid: (SEQ/64, BATCH*NHEAD); block 256.  BQ = BK = 64, HD = 64.
#define ATTN_SMEM_FLOATS (3 * 64 * 65 + 64 * 64 + 3 * 64)
__global__ __launch_bounds__(256) void attn_kernel()
{
    extern __shared__ float sm[];
    float* Qt   = sm;                    // [64 d][65] transposed, pre-scaled
    float* Kt   = Qt + 64 * 65;          // [64 d][65] transposed
    float* Vs   = Kt + 64 * 65;          // [64 k][64 d]
    float* Ss   = Vs + 64 * 64;          // [64 q][65 k]
    float* rowM = Ss + 64 * 65;
    float* rowL = rowM + 64;
    float* rowS = rowL + 64;

    int t     = threadIdx.x;
    int qtile = blockIdx.x;
    int bh    = blockIdx.y;
    int b     = bh >> 4, h = bh & 15;
    size_t baseBH = (size_t)b * SEQ * (3 * DM) + (size_t)h * HD;
    int q0 = qtile * 64;
    int ty = t >> 4, tx = t & 15;

    // load Q tile transposed + scaled by 1/sqrt(64)
    for (int i = t; i < 64 * 16; i += 256) {
        int r = i >> 4, c4 = (i & 15) * 4;
        float4 v = *(const float4*)&g_qkv[baseBH + (size_t)(q0 + r) * (3 * DM) + c4];
        Qt[(c4 + 0) * 65 + r] = v.x * 0.125f;
        Qt[(c4 + 1) * 65 + r] = v.y * 0.125f;
        Qt[(c4 + 2) * 65 + r] = v.z * 0.125f;
        Qt[(c4 + 3) * 65 + r] = v.w * 0.125f;
    }
    if (t < 64) { rowM[t] = -1e30f; rowL[t] = 0.f; }

    float acc[4][4];
    #pragma unroll
    for (int i = 0; i < 4; i++)
        #pragma unroll
        for (int j = 0; j < 4; j++) acc[i][j] = 0.f;

    for (int j0t = 0; j0t <= qtile; ++j0t) {
        int k0 = j0t * 64;
        // load K (transposed) and V tiles
        for (int i = t; i < 64 * 16; i += 256) {
            int r = i >> 4, c4 = (i & 15) * 4;
            size_t base = baseBH + (size_t)(k0 + r) * (3 * DM);
            float4 kv = *(const float4*)&g_qkv[base + DM + c4];
            Kt[(c4 + 0) * 65 + r] = kv.x;
            Kt[(c4 + 1) * 65 + r] = kv.y;
            Kt[(c4 + 2) * 65 + r] = kv.z;
            Kt[(c4 + 3) * 65 + r] = kv.w;
            float4 vv = *(const float4*)&g_qkv[base + 2 * DM + c4];
            *(float4*)&Vs[r * 64 + c4] = vv;
        }
        __syncthreads();

        // S = Q K^T  (4x4 per thread)
        float s[4][4];
        #pragma unroll
        for (int i = 0; i < 4; i++)
            #pragma unroll
            for (int j = 0; j < 4; j++) s[i][j] = 0.f;
        #pragma unroll 8
        for (int d = 0; d < 64; d++) {
            float a0 = Qt[d * 65 + ty * 4 + 0];
            float a1 = Qt[d * 65 + ty * 4 + 1];
            float a2 = Qt[d * 65 + ty * 4 + 2];
            float a3 = Qt[d * 65 + ty * 4 + 3];
            float b0 = Kt[d * 65 + tx * 4 + 0];
            float b1 = Kt[d * 65 + tx * 4 + 1];
            float b2 = Kt[d * 65 + tx * 4 + 2];
            float b3 = Kt[d * 65 + tx * 4 + 3];
            s[0][0] = fmaf(a0, b0, s[0][0]); s[0][1] = fmaf(a0, b1, s[0][1]);
            s[0][2] = fmaf(a0, b2, s[0][2]); s[0][3] = fmaf(a0, b3, s[0][3]);
            s[1][0] = fmaf(a1, b0, s[1][0]); s[1][1] = fmaf(a1, b1, s[1][1]);
            s[1][2] = fmaf(a1, b2, s[1][2]); s[1][3] = fmaf(a1, b3, s[1][3]);
            s[2][0] = fmaf(a2, b0, s[2][0]); s[2][1] = fmaf(a2, b1, s[2][1]);
            s[2][2] = fmaf(a2, b2, s[2][2]); s[2][3] = fmaf(a2, b3, s[2][3]);
            s[3][0] = fmaf(a3, b0, s[3][0]); s[3][1] = fmaf(a3, b1, s[3][1]);
            s[3][2] = fmaf(a3, b2, s[3][2]); s[3][3] = fmaf(a3, b3, s[3][3]);
        }
        if (j0t == qtile) {                     // causal mask on diagonal tile
            #pragma unroll
            for (int i = 0; i < 4; i++)
                #pragma unroll
                for (int j = 0; j < 4; j++) {
                    int qi = q0 + ty * 4 + i, ki = k0 + tx * 4 + j;
                    if (ki > qi) s[i][j] = -1e30f;
                }
        }
        #pragma unroll
        for (int i = 0; i < 4; i++)
            #pragma unroll
            for (int j = 0; j < 4; j++)
                Ss[(ty * 4 + i) * 65 + tx * 4 + j] = s[i][j];
        __syncthreads();

        // online softmax per row (64 threads)
        if (t < 64) {
            float m_old = rowM[t], m = m_old;
            #pragma unroll 8
            for (int k = 0; k < 64; k++) m = fmaxf(m, Ss[t * 65 + k]);
            float scl = __expf(m_old - m);
            float l = rowL[t] * scl;
            #pragma unroll 8
            for (int k = 0; k < 64; k++) {
                float p = __expf(Ss[t * 65 + k] - m);
                Ss[t * 65 + k] = p;
                l += p;
            }
            rowM[t] = m; rowL[t] = l; rowS[t] = scl;
        }
        __syncthreads();

        // rescale acc + accumulate P @ V
        float sci[4];
        #pragma unroll
        for (int i = 0; i < 4; i++) sci[i] = rowS[ty * 4 + i];
        #pragma unroll
        for (int i = 0; i < 4; i++)
            #pragma unroll
            for (int j = 0; j < 4; j++) acc[i][j] *= sci[i];
        #pragma unroll 8
        for (int k = 0; k < 64; k++) {
            float p0 = Ss[(ty * 4 + 0) * 65 + k];
            float p1 = Ss[(ty * 4 + 1) * 65 + k];
            float p2 = Ss[(ty * 4 + 2) * 65 + k];
            float p3 = Ss[(ty * 4 + 3) * 65 + k];
            float v0 = Vs[k * 64 + tx * 4 + 0];
            float v1 = Vs[k * 64 + tx * 4 + 1];
            float v2 = Vs[k * 64 + tx * 4 + 2];
            float v3 = Vs[k * 64 + tx * 4 + 3];
            acc[0][0] = fmaf(p0, v0, acc[0][0]); acc[0][1] = fmaf(p0, v1, acc[0][1]);
            acc[0][2] = fmaf(p0, v2, acc[0][2]); acc[0][3] = fmaf(p0, v3, acc[0][3]);
            acc[1][0] = fmaf(p1, v0, acc[1][0]); acc[1][1] = fmaf(p1, v1, acc[1][1]);
            acc[1][2] = fmaf(p1, v2, acc[1][2]); acc[1][3] = fmaf(p1, v3, acc[1][3]);
            acc[2][0] = fmaf(p2, v0, acc[2][0]); acc[2][1] = fmaf(p2, v1, acc[2][1]);
            acc[2][2] = fmaf(p2, v2, acc[2][2]); acc[2][3] = fmaf(p2, v3, acc[2][3]);
            acc[3][0] = fmaf(p3, v0, acc[3][0]); acc[3][1] = fmaf(p3, v1, acc[3][1]);
            acc[3][2] = fmaf(p3, v2, acc[3][2]); acc[3][3] = fmaf(p3, v3, acc[3][3]);
        }
        __syncthreads();
    }

    // write O = acc / l  into [B,S,D] head-concat layout
    float invl[4];
    #pragma unroll
    for (int i = 0; i < 4; i++) invl[i] = 1.0f / rowL[ty * 4 + i];
    #pragma unroll
    for (int i = 0; i < 4; i++) {
        int q = q0 + ty * 4 + i;
        float* orow = &g_attn[(size_t)(b * SEQ + q) * DM + h * HD + tx * 4];
        #pragma unroll
        for (int j = 0; j < 4; j++) orow[j] = acc[i][j] * invl[i];
    }
}

// ---------------- launch ---------------------------------------------------
extern "C" void kernel_launch(void* const* d_in, const int* in_sizes, int n_in,
                              void* d_out, int out_size)
{
    (void)in_sizes; (void)n_in; (void)out_size;
    const float* x     = (const float*)d_in[0];
    const float* w_qkv = (const float*)d_in[1];
    const float* b_qkv = (const float*)d_in[2];
    const float* w_out = (const float*)d_in[3];
    const float* b_out = (const float*)d_in[4];
    const float* w_fc1 = (const float*)d_in[5];
    const float* b_fc1 = (const float*)d_in[6];
    const float* w_fc2 = (const float*)d_in[7];
    const float* b_fc2 = (const float*)d_in[8];
    const float* ln1s  = (const float*)d_in[9];
    const float* ln1b  = (const float*)d_in[10];
    const float* ln2s  = (const float*)d_in[11];
    const float* ln2b  = (const float*)d_in[12];
    float* out = (float*)d_out;

    float *xn, *qkv, *attn, *res1, *ff;
    cudaGetSymbolAddress((void**)&xn,   g_xn);
    cudaGetSymbolAddress((void**)&qkv,  g_qkv);
    cudaGetSymbolAddress((void**)&attn, g_attn);
    cudaGetSymbolAddress((void**)&res1, g_res1);
    cudaGetSymbolAddress((void**)&ff,   g_ff);

    const int ATTN_SMEM_BYTES = ATTN_SMEM_FLOATS * 4;  // 67072
    cudaFuncSetAttribute(attn_kernel,
                         cudaFuncAttributeMaxDynamicSharedMemorySize,
                         ATTN_SMEM_BYTES);

    // 1. LN1
    ln_kernel<<<NROWS, 256>>>(x, ln1s, ln1b, xn);
    // 2. QKV projection
    gemm_tf32_kernel<<<dim3(3 * DM / 128, NROWS / 128), 256>>>(
        xn, w_qkv, b_qkv, (const float*)0, qkv, NROWS, 3 * DM, DM, 0);
    // 3. causal flash attention
    attn_kernel<<<dim3(SEQ / 64, BATCH * NHEAD), 256, ATTN_SMEM_BYTES>>>();
    // 4. out projection + residual(x)
    gemm_tf32_kernel<<<dim3(DM / 128, NROWS / 128), 256>>>(
        attn, w_out, b_out, x, res1, NROWS, DM, DM, 1);
    // 5. LN2
    ln_kernel<<<NROWS, 256>>>(res1, ln2s, ln2b, xn);
    // 6. FC1 + gelu
    gemm_tf32_kernel<<<dim3(DFF / 128, NROWS / 128), 256>>>(
        xn, w_fc1, b_fc1, (const float*)0, ff, NROWS, DFF, DM, 2);
    // 7. FC2 + residual(res1) -> out
    gemm_tf32_kernel<<<dim3(DM / 128, NROWS / 128), 256>>>(
        ff, w_fc2, b_fc2, res1, out, NROWS, DM, DFF, 1);
}

// round 4
// speedup vs baseline: 2.2604x; 1.1598x over previous
#include <cuda_runtime.h>
#include <math.h>
#include <stdint.h>

#define BATCH 4
#define SEQ   2048
#define DM    1024
#define DFF   4096
#define NHEAD 16
#define HD    64
#define NROWS (BATCH*SEQ)   /* 8192 */

// ---------------- scratch (device globals; no allocation allowed) ----------
__device__ float g_xn   [(size_t)NROWS * DM];
__device__ float g_qkv  [(size_t)NROWS * 3 * DM];
__device__ float g_attn [(size_t)NROWS * DM];
__device__ float g_res1 [(size_t)NROWS * DM];
__device__ float g_ff   [(size_t)NROWS * DFF];
// transposed (N-major, K-contig) tf32-rounded weights
__device__ float g_wqkvT[(size_t)3 * DM * DM];
__device__ float g_woutT[(size_t)DM * DM];
__device__ float g_wfc1T[(size_t)DFF * DM];
__device__ float g_wfc2T[(size_t)DM * DFF];

// ---------------- helpers ---------------------------------------------------
__device__ __forceinline__ float tf32r(float x) {
    uint32_t u;
    asm("cvt.rna.tf32.f32 %0, %1;" : "=r"(u) : "f"(x));
    return __uint_as_float(u);
}
__device__ __forceinline__ void cpa16(uint32_t dst, const void* src) {
    asm volatile("cp.async.cg.shared.global [%0], [%1], 16;" :: "r"(dst), "l"(src));
}
#define CP_COMMIT() asm volatile("cp.async.commit_group;" ::: "memory")
#define CP_WAIT(n)  asm volatile("cp.async.wait_group %0;" :: "n"(n) : "memory")

__device__ __forceinline__ uint32_t smem_u32(const void* p) {
    uint32_t a;
    asm("{ .reg .u64 t; cvta.to.shared.u64 t, %1; cvt.u32.u64 %0, t; }" : "=r"(a) : "l"(p));
    return a;
}

__device__ __forceinline__ float gelu_f(float x) {
    float x3 = x * x * x;
    return 0.5f * x * (1.0f + tanhf(0.7978845608028654f * (x + 0.044715f * x3)));
}

// ---------------- weight transpose + tf32 round -----------------------------
// in[K][N] row-major -> out[N][K] (K contiguous), tf32-rounded
__global__ __launch_bounds__(256) void transpose_rna(
    const float* __restrict__ in, float* __restrict__ out, int K, int N)
{
    __shared__ float s[32 * 33];
    int t = threadIdx.x;
    int n0 = blockIdx.x * 32, k0 = blockIdx.y * 32;
    int r = t >> 3, c = (t & 7) * 4;
    float4 v = *(const float4*)(in + (size_t)(k0 + r) * N + n0 + c);
    s[(c + 0) * 33 + r] = v.x;
    s[(c + 1) * 33 + r] = v.y;
    s[(c + 2) * 33 + r] = v.z;
    s[(c + 3) * 33 + r] = v.w;
    __syncthreads();
    float4 o;
    o.x = tf32r(s[r * 33 + c + 0]);
    o.y = tf32r(s[r * 33 + c + 1]);
    o.z = tf32r(s[r * 33 + c + 2]);
    o.w = tf32r(s[r * 33 + c + 3]);
    *(float4*)(out + (size_t)(n0 + r) * K + k0 + c) = o;
}

// ---------------- LayerNorm (outputs tf32-rounded) --------------------------
__global__ __launch_bounds__(256) void ln_kernel(
    const float* __restrict__ x, const float* __restrict__ scale,
    const float* __restrict__ bias, float* __restrict__ out)
{
    int row = blockIdx.x;
    const float4* xr = (const float4*)(x + (size_t)row * DM);
    float4 v = xr[threadIdx.x];
    float s  = v.x + v.y + v.z + v.w;
    float ss = v.x*v.x + v.y*v.y + v.z*v.z + v.w*v.w;
    #pragma unroll
    for (int o = 16; o > 0; o >>= 1) {
        s  += __shfl_xor_sync(0xffffffffu, s,  o);
        ss += __shfl_xor_sync(0xffffffffu, ss, o);
    }
    __shared__ float smS[8], smSS[8];
    __shared__ float sMean, sRstd;
    int w = threadIdx.x >> 5, lane = threadIdx.x & 31;
    if (lane == 0) { smS[w] = s; smSS[w] = ss; }
    __syncthreads();
    if (threadIdx.x == 0) {
        float S = 0.f, SS = 0.f;
        #pragma unroll
        for (int i = 0; i < 8; i++) { S += smS[i]; SS += smSS[i]; }
        float mean = S * (1.0f / DM);
        float var  = SS * (1.0f / DM) - mean * mean;
        sMean = mean; sRstd = rsqrtf(var + 1e-6f);
    }
    __syncthreads();
    float mean = sMean, rstd = sRstd;
    int c = threadIdx.x * 4;
    float4 sc = *(const float4*)(scale + c);
    float4 bi = *(const float4*)(bias  + c);
    float4 o;
    o.x = tf32r((v.x - mean) * rstd * sc.x + bi.x);
    o.y = tf32r((v.y - mean) * rstd * sc.y + bi.y);
    o.z = tf32r((v.z - mean) * rstd * sc.z + bi.z);
    o.w = tf32r((v.w - mean) * rstd * sc.w + bi.w);
    ((float4*)(out + (size_t)row * DM))[threadIdx.x] = o;
}

// ---------------- TF32 mma.sync GEMM with cp.async pipeline -----------------
// C[M,N] = A[M,K] @ Bt[N,K]^T + bias (+res/gelu). A, Bt pre-rounded to tf32.
// Block 128x128, BK=16, 8 warps (2x4), warp tile 64x32, 3-stage cp.async.
// smem per stage: A[128][20] + B[128][20] floats; fragment LDS conflict-free.
#define SK    20
#define NSTG  3
#define STGF  (256 * SK)                 /* floats per stage (A+B) */
#define GSM_BYTES (NSTG * STGF * 4)      /* 61440 */

__global__ __launch_bounds__(256, 2) void gemm_tf32(
    const float* __restrict__ A, const float* __restrict__ Bt,
    const float* __restrict__ bias, const float* __restrict__ R,
    float* __restrict__ C, int M, int N, int K, int epi)
{
    extern __shared__ float sm[];
    const uint32_t sb = smem_u32(sm);

    const int t  = threadIdx.x;
    const int m0 = blockIdx.y * 128, n0 = blockIdx.x * 128;
    const int w  = t >> 5, lane = t & 31;
    const int wr = w >> 2, wc = w & 3;        // 2 x 4 warps
    const int wm = wr * 64, wn = wc * 32;     // warp tile 64x32
    const int lr = lane >> 2, lc = lane & 3;

    float c[4][4][4];
    #pragma unroll
    for (int mf = 0; mf < 4; mf++)
        #pragma unroll
        for (int nf = 0; nf < 4; nf++)
            #pragma unroll
            for (int i = 0; i < 4; i++) c[mf][nf][i] = 0.f;

    // loader: 2 A granules + 2 B granules (16B each) per thread per stage
    const int grow = t >> 2;          // 0..63 base row
    const int gkc  = (t & 3) * 4;     // k offset in floats (0,4,8,12)
    const float* Ap0 = A  + (size_t)(m0 + grow)      * K + gkc;
    const float* Ap1 = A  + (size_t)(m0 + 64 + grow) * K + gkc;
    const float* Bp0 = Bt + (size_t)(n0 + grow)      * K + gkc;
    const float* Bp1 = Bt + (size_t)(n0 + 64 + grow) * K + gkc;
    const uint32_t dA0 = sb + (grow * SK + gkc) * 4;
    const uint32_t dA1 = sb + ((grow + 64) * SK + gkc) * 4;
    const uint32_t dB0 = sb + ((128 + grow) * SK + gkc) * 4;
    const uint32_t dB1 = sb + ((128 + 64 + grow) * SK + gkc) * 4;

    const int NC = K >> 4;

    #define LOAD_STAGE(st, cc) do {                                   \
        uint32_t so_ = (uint32_t)(st) * (STGF * 4);                   \
        size_t ko_ = (size_t)(cc) << 4;                               \
        cpa16(dA0 + so_, Ap0 + ko_);                                  \
        cpa16(dA1 + so_, Ap1 + ko_);                                  \
        cpa16(dB0 + so_, Bp0 + ko_);                                  \
        cpa16(dB1 + so_, Bp1 + ko_);                                  \
        CP_COMMIT();                                                  \
    } while (0)

    LOAD_STAGE(0, 0);
    LOAD_STAGE(1, 1);

    int st = 0;
    for (int cc = 0; cc < NC; cc++) {
        CP_WAIT(1);
        __syncthreads();

        const float* as = sm + st * STGF;
        const float* bs = as + 128 * SK;
        #pragma unroll
        for (int ks = 0; ks < 16; ks += 8) {
            float a[4][4], b[4][2];
            #pragma unroll
            for (int mf = 0; mf < 4; mf++) {
                int mr = wm + mf * 16 + lr;
                a[mf][0] = as[mr * SK + ks + lc];
                a[mf][1] = as[(mr + 8) * SK + ks + lc];
                a[mf][2] = as[mr * SK + ks + lc + 4];
                a[mf][3] = as[(mr + 8) * SK + ks + lc + 4];
            }
            #pragma unroll
            for (int nf = 0; nf < 4; nf++) {
                int nr = wn + nf * 8 + lr;
                b[nf][0] = bs[nr * SK + ks + lc];
                b[nf][1] = bs[nr * SK + ks + lc + 4];
            }
            #pragma unroll
            for (int mf = 0; mf < 4; mf++)
                #pragma unroll
                for (int nf = 0; nf < 4; nf++) {
                    asm volatile(
                        "mma.sync.aligned.m16n8k8.row.col.f32.tf32.tf32.f32 "
                        "{%0,%1,%2,%3}, {%4,%5,%6,%7}, {%8,%9}, {%0,%1,%2,%3};\n"
                        : "+f"(c[mf][nf][0]), "+f"(c[mf][nf][1]),
                          "+f"(c[mf][nf][2]), "+f"(c[mf][nf][3])
                        : "r"(__float_as_uint(a[mf][0])),
                          "r"(__float_as_uint(a[mf][1])),
                          "r"(__float_as_uint(a[mf][2])),
                          "r"(__float_as_uint(a[mf][3])),
                          "r"(__float_as_uint(b[nf][0])),
                          "r"(__float_as_uint(b[nf][1])));
                }
        }
        __syncthreads();
        if (cc + 2 < NC) LOAD_STAGE((st + 2) % NSTG, cc + 2);
        else             CP_COMMIT();
        st = (st + 1) % NSTG;
    }
    #undef LOAD_STAGE

    // -------- epilogue --------
    #pragma unroll
    for (int mf = 0; mf < 4; mf++) {
        #pragma unroll
        for (int nf = 0; nf < 4; nf++) {
            int row = m0 + wm + mf * 16 + lr;
            int col = n0 + wn + nf * 8 + lc * 2;
            float b0 = bias[col], b1 = bias[col + 1];
            float v0 = c[mf][nf][0] + b0;
            float v1 = c[mf][nf][1] + b1;
            float v2 = c[mf][nf][2] + b0;
            float v3 = c[mf][nf][3] + b1;
            if (epi == 1) {
                const float* r0 = R + (size_t)row * N + col;
                const float* r1 = R + (size_t)(row + 8) * N + col;
                v0 += r0[0]; v1 += r0[1];
                v2 += r1[0]; v3 += r1[1];
            } else if (epi == 2) {
                v0 = tf32r(gelu_f(v0)); v1 = tf32r(gelu_f(v1));
                v2 = tf32r(gelu_f(v2)); v3 = tf32r(gelu_f(v3));
            }
            *(float2*)(C + (size_t)row * N + col)       = make_float2(v0, v1);
            *(float2*)(C + (size_t)(row + 8) * N + col) = make_float2(v2, v3);
        }
    }
}

// ---------------- Flash-attention (fp32, causal) ---------------------------
#define ATTN_SMEM_FLOATS (3 * 64 * 65 + 64 * 64 + 3 * 64)
__global__ __launch_bounds__(256) void attn_kernel()
{
    extern __shared__ float sm[];
    float* Qt   = sm;
    float* Kt   = Qt + 64 * 65;
    float* Vs   = Kt + 64 * 65;
    float* Ss   = Vs + 64 * 64;
    float* rowM = Ss + 64 * 65;
    float* rowL = rowM + 64;
    float* rowS = rowL + 64;

    int t = threadIdx.x;
    int qtile = blockIdx.x, bh = blockIdx.y;
    int b = bh >> 4, h = bh & 15;
    size_t baseBH = (size_t)b * SEQ * (3 * DM) + (size_t)h * HD;
    int q0 = qtile * 64;
    int ty = t >> 4, tx = t & 15;

    for (int i = t; i < 64 * 16; i += 256) {
        int r = i >> 4, c4 = (i & 15) * 4;
        float4 v = *(const float4*)&g_qkv[baseBH + (size_t)(q0 + r) * (3 * DM) + c4];
        Qt[(c4 + 0) * 65 + r] = v.x * 0.125f;
        Qt[(c4 + 1) * 65 + r] = v.y * 0.125f;
        Qt[(c4 + 2) * 65 + r] = v.z * 0.125f;
        Qt[(c4 + 3) * 65 + r] = v.w * 0.125f;
    }
    if (t < 64) { rowM[t] = -1e30f; rowL[t] = 0.f; }

    float acc[4][4];
    #pragma unroll
    for (int i = 0; i < 4; i++)
        #pragma unroll
        for (int j = 0; j < 4; j++) acc[i][j] = 0.f;

    for (int j0t = 0; j0t <= qtile; ++j0t) {
        int k0 = j0t * 64;
        for (int i = t; i < 64 * 16; i += 256) {
            int r = i >> 4, c4 = (i & 15) * 4;
            size_t base = baseBH + (size_t)(k0 + r) * (3 * DM);
            float4 kv = *(const float4*)&g_qkv[base + DM + c4];
            Kt[(c4 + 0) * 65 + r] = kv.x;
            Kt[(c4 + 1) * 65 + r] = kv.y;
            Kt[(c4 + 2) * 65 + r] = kv.z;
            Kt[(c4 + 3) * 65 + r] = kv.w;
            float4 vv = *(const float4*)&g_qkv[base + 2 * DM + c4];
            *(float4*)&Vs[r * 64 + c4] = vv;
        }
        __syncthreads();

        float s[4][4];
        #pragma unroll
        for (int i = 0; i < 4; i++)
            #pragma unroll
            for (int j = 0; j < 4; j++) s[i][j] = 0.f;
        #pragma unroll 8
        for (int d = 0; d < 64; d++) {
            float a0 = Qt[d * 65 + ty * 4 + 0];
            float a1 = Qt[d * 65 + ty * 4 + 1];
            float a2 = Qt[d * 65 + ty * 4 + 2];
            float a3 = Qt[d * 65 + ty * 4 + 3];
            float b0 = Kt[d * 65 + tx * 4 + 0];
            float b1 = Kt[d * 65 + tx * 4 + 1];
            float b2 = Kt[d * 65 + tx * 4 + 2];
            float b3 = Kt[d * 65 + tx * 4 + 3];
            s[0][0] = fmaf(a0, b0, s[0][0]); s[0][1] = fmaf(a0, b1, s[0][1]);
            s[0][2] = fmaf(a0, b2, s[0][2]); s[0][3] = fmaf(a0, b3, s[0][3]);
            s[1][0] = fmaf(a1, b0, s[1][0]); s[1][1] = fmaf(a1, b1, s[1][1]);
            s[1][2] = fmaf(a1, b2, s[1][2]); s[1][3] = fmaf(a1, b3, s[1][3]);
            s[2][0] = fmaf(a2, b0, s[2][0]); s[2][1] = fmaf(a2, b1, s[2][1]);
            s[2][2] = fmaf(a2, b2, s[2][2]); s[2][3] = fmaf(a2, b3, s[2][3]);
            s[3][0] = fmaf(a3, b0, s[3][0]); s[3][1] = fmaf(a3, b1, s[3][1]);
            s[3][2] = fmaf(a3, b2, s[3][2]); s[3][3] = fmaf(a3, b3, s[3][3]);
        }
        if (j0t == qtile) {
            #pragma unroll
            for (int i = 0; i < 4; i++)
                #pragma unroll
                for (int j = 0; j < 4; j++) {
                    int qi = q0 + ty * 4 + i, ki = k0 + tx * 4 + j;
                    if (ki > qi) s[i][j] = -1e30f;
                }
        }
        #pragma unroll
        for (int i = 0; i < 4; i++)
            #pragma unroll
            for (int j = 0; j < 4; j++)
                Ss[(ty * 4 + i) * 65 + tx * 4 + j] = s[i][j];
        __syncthreads();

        // parallel online softmax: 4 threads per row
        {
            int row = t >> 2, part = t & 3;
            float m_old = rowM[row];
            float mloc = -1e30f;
            const float* srow = &Ss[row * 65 + part * 16];
            #pragma unroll
            for (int k = 0; k < 16; k++) mloc = fmaxf(mloc, srow[k]);
            mloc = fmaxf(mloc, __shfl_xor_sync(0xffffffffu, mloc, 1));
            mloc = fmaxf(mloc, __shfl_xor_sync(0xffffffffu, mloc, 2));
            float m = fmaxf(m_old, mloc);
            float lpart = 0.f;
            float* srw = &Ss[row * 65 + part * 16];
            #pragma unroll
            for (int k = 0; k < 16; k++) {
                float p = __expf(srw[k] - m);
                srw[k] = p;
                lpart += p;
            }
            lpart += __shfl_xor_sync(0xffffffffu, lpart, 1);
            lpart += __shfl_xor_sync(0xffffffffu, lpart, 2);
            if (part == 0) {
                float scl = __expf(m_old - m);
                rowM[row] = m;
                rowL[row] = rowL[row] * scl + lpart;
                rowS[row] = scl;
            }
        }
        __syncthreads();

        float sci[4];
        #pragma unroll
        for (int i = 0; i < 4; i++) sci[i] = rowS[ty * 4 + i];
        #pragma unroll
        for (int i = 0; i < 4; i++)
            #pragma unroll
            for (int j = 0; j < 4; j++) acc[i][j] *= sci[i];
        #pragma unroll 8
        for (int k = 0; k < 64; k++) {
            float p0 = Ss[(ty * 4 + 0) * 65 + k];
            float p1 = Ss[(ty * 4 + 1) * 65 + k];
            float p2 = Ss[(ty * 4 + 2) * 65 + k];
            float p3 = Ss[(ty * 4 + 3) * 65 + k];
            float v0 = Vs[k * 64 + tx * 4 + 0];
            float v1 = Vs[k * 64 + tx * 4 + 1];
            float v2 = Vs[k * 64 + tx * 4 + 2];
            float v3 = Vs[k * 64 + tx * 4 + 3];
            acc[0][0] = fmaf(p0, v0, acc[0][0]); acc[0][1] = fmaf(p0, v1, acc[0][1]);
            acc[0][2] = fmaf(p0, v2, acc[0][2]); acc[0][3] = fmaf(p0, v3, acc[0][3]);
            acc[1][0] = fmaf(p1, v0, acc[1][0]); acc[1][1] = fmaf(p1, v1, acc[1][1]);
            acc[1][2] = fmaf(p1, v2, acc[1][2]); acc[1][3] = fmaf(p1, v3, acc[1][3]);
            acc[2][0] = fmaf(p2, v0, acc[2][0]); acc[2][1] = fmaf(p2, v1, acc[2][1]);
            acc[2][2] = fmaf(p2, v2, acc[2][2]); acc[2][3] = fmaf(p2, v3, acc[2][3]);
            acc[3][0] = fmaf(p3, v0, acc[3][0]); acc[3][1] = fmaf(p3, v1, acc[3][1]);
            acc[3][2] = fmaf(p3, v2, acc[3][2]); acc[3][3] = fmaf(p3, v3, acc[3][3]);
        }
        __syncthreads();
    }

    float invl[4];
    #pragma unroll
    for (int i = 0; i < 4; i++) invl[i] = 1.0f / rowL[ty * 4 + i];
    #pragma unroll
    for (int i = 0; i < 4; i++) {
        int q = q0 + ty * 4 + i;
        float* orow = &g_attn[(size_t)(b * SEQ + q) * DM + h * HD + tx * 4];
        #pragma unroll
        for (int j = 0; j < 4; j++) orow[j] = tf32r(acc[i][j] * invl[i]);
    }
}

// ---------------- launch ---------------------------------------------------
extern "C" void kernel_launch(void* const* d_in, const int* in_sizes, int n_in,
                              void* d_out, int out_size)
{
    (void)in_sizes; (void)n_in; (void)out_size;
    const float* x     = (const float*)d_in[0];
    const float* w_qkv = (const float*)d_in[1];
    const float* b_qkv = (const float*)d_in[2];
    const float* w_out = (const float*)d_in[3];
    const float* b_out = (const float*)d_in[4];
    const float* w_fc1 = (const float*)d_in[5];
    const float* b_fc1 = (const float*)d_in[6];
    const float* w_fc2 = (const float*)d_in[7];
    const float* b_fc2 = (const float*)d_in[8];
    const float* ln1s  = (const float*)d_in[9];
    const float* ln1b  = (const float*)d_in[10];
    const float* ln2s  = (const float*)d_in[11];
    const float* ln2b  = (const float*)d_in[12];
    float* out = (float*)d_out;

    float *xn, *qkv, *attn, *res1, *ff, *wqkvT, *woutT, *wfc1T, *wfc2T;
    cudaGetSymbolAddress((void**)&xn,    g_xn);
    cudaGetSymbolAddress((void**)&qkv,   g_qkv);
    cudaGetSymbolAddress((void**)&attn,  g_attn);
    cudaGetSymbolAddress((void**)&res1,  g_res1);
    cudaGetSymbolAddress((void**)&ff,    g_ff);
    cudaGetSymbolAddress((void**)&wqkvT, g_wqkvT);
    cudaGetSymbolAddress((void**)&woutT, g_woutT);
    cudaGetSymbolAddress((void**)&wfc1T, g_wfc1T);
    cudaGetSymbolAddress((void**)&wfc2T, g_wfc2T);

    cudaFuncSetAttribute(gemm_tf32,
        cudaFuncAttributeMaxDynamicSharedMemorySize, GSM_BYTES);
    cudaFuncSetAttribute(attn_kernel,
        cudaFuncAttributeMaxDynamicSharedMemorySize, ATTN_SMEM_FLOATS * 4);

    // 0. weight transposes (tf32-rounded, K-contiguous)
    transpose_rna<<<dim3(3 * DM / 32, DM / 32), 256>>>(w_qkv, wqkvT, DM, 3 * DM);
    transpose_rna<<<dim3(DM / 32, DM / 32), 256>>>(w_out, woutT, DM, DM);
    transpose_rna<<<dim3(DFF / 32, DM / 32), 256>>>(w_fc1, wfc1T, DM, DFF);
    transpose_rna<<<dim3(DM / 32, DFF / 32), 256>>>(w_fc2, wfc2T, DFF, DM);

    // 1. LN1
    ln_kernel<<<NROWS, 256>>>(x, ln1s, ln1b, xn);
    // 2. QKV projection
    gemm_tf32<<<dim3(3 * DM / 128, NROWS / 128), 256, GSM_BYTES>>>(
        xn, wqkvT, b_qkv, (const float*)0, qkv, NROWS, 3 * DM, DM, 0);
    // 3. causal flash attention
    attn_kernel<<<dim3(SEQ / 64, BATCH * NHEAD), 256, ATTN_SMEM_FLOATS * 4>>>();
    // 4. out projection + residual(x)
    gemm_tf32<<<dim3(DM / 128, NROWS / 128), 256, GSM_BYTES>>>(
        attn, woutT, b_out, x, res1, NROWS, DM, DM, 1);
    // 5. LN2
    ln_kernel<<<NROWS, 256>>>(res1, ln2s, ln2b, xn);
    // 6. FC1 + gelu
    gemm_tf32<<<dim3(DFF / 128, NROWS / 128), 256, GSM_BYTES>>>(
        xn, wfc1T, b_fc1, (const float*)0, ff, NROWS, DFF, DM, 2);
    // 7. FC2 + residual(res1) -> out
    gemm_tf32<<<dim3(DM / 128, NROWS / 128), 256, GSM_BYTES>>>(
        ff, wfc2T, b_fc2, res1, out, NROWS, DM, DFF, 1);
}

// round 5
// speedup vs baseline: 3.0540x; 1.3511x over previous
#include <cuda_runtime.h>
#include <math.h>
#include <stdint.h>

#define BATCH 4
#define SEQ   2048
#define DM    1024
#define DFF   4096
#define NHEAD 16
#define HD    64
#define NROWS (BATCH*SEQ)   /* 8192 */

// ---------------- scratch (device globals; no allocation allowed) ----------
__device__ float g_xn   [(size_t)NROWS * DM];
__device__ float g_qkv  [(size_t)NROWS * 3 * DM];
__device__ float g_attn [(size_t)NROWS * DM];
__device__ float g_res1 [(size_t)NROWS * DM];
__device__ float g_ff   [(size_t)NROWS * DFF];
// transposed (N-major, K-contig) tf32-rounded weights
__device__ float g_wqkvT[(size_t)3 * DM * DM];
__device__ float g_woutT[(size_t)DM * DM];
__device__ float g_wfc1T[(size_t)DFF * DM];
__device__ float g_wfc2T[(size_t)DM * DFF];

// ---------------- helpers ---------------------------------------------------
__device__ __forceinline__ float tf32r(float x) {
    uint32_t u;
    asm("cvt.rna.tf32.f32 %0, %1;" : "=r"(u) : "f"(x));
    return __uint_as_float(u);
}
__device__ __forceinline__ void cpa16(uint32_t dst, const void* src) {
    asm volatile("cp.async.cg.shared.global [%0], [%1], 16;" :: "r"(dst), "l"(src));
}
#define CP_COMMIT() asm volatile("cp.async.commit_group;" ::: "memory")
#define CP_WAIT(n)  asm volatile("cp.async.wait_group %0;" :: "n"(n) : "memory")

__device__ __forceinline__ uint32_t smem_u32(const void* p) {
    uint32_t a;
    asm("{ .reg .u64 t; cvta.to.shared.u64 t, %1; cvt.u32.u64 %0, t; }" : "=r"(a) : "l"(p));
    return a;
}

__device__ __forceinline__ float gelu_f(float x) {
    float x3 = x * x * x;
    return 0.5f * x * (1.0f + tanhf(0.7978845608028654f * (x + 0.044715f * x3)));
}

#define MMA_TF32(c, a0,a1,a2,a3, b0,b1)                                     \
    asm volatile(                                                           \
        "mma.sync.aligned.m16n8k8.row.col.f32.tf32.tf32.f32 "               \
        "{%0,%1,%2,%3}, {%4,%5,%6,%7}, {%8,%9}, {%0,%1,%2,%3};\n"           \
        : "+f"((c)[0]), "+f"((c)[1]), "+f"((c)[2]), "+f"((c)[3])            \
        : "r"(__float_as_uint(a0)), "r"(__float_as_uint(a1)),               \
          "r"(__float_as_uint(a2)), "r"(__float_as_uint(a3)),               \
          "r"(__float_as_uint(b0)), "r"(__float_as_uint(b1)))

// ---------------- weight transpose + tf32 round -----------------------------
__global__ __launch_bounds__(256) void transpose_rna(
    const float* __restrict__ in, float* __restrict__ out, int K, int N)
{
    __shared__ float s[32 * 33];
    int t = threadIdx.x;
    int n0 = blockIdx.x * 32, k0 = blockIdx.y * 32;
    int r = t >> 3, c = (t & 7) * 4;
    float4 v = *(const float4*)(in + (size_t)(k0 + r) * N + n0 + c);
    s[(c + 0) * 33 + r] = v.x;
    s[(c + 1) * 33 + r] = v.y;
    s[(c + 2) * 33 + r] = v.z;
    s[(c + 3) * 33 + r] = v.w;
    __syncthreads();
    float4 o;
    o.x = tf32r(s[r * 33 + c + 0]);
    o.y = tf32r(s[r * 33 + c + 1]);
    o.z = tf32r(s[r * 33 + c + 2]);
    o.w = tf32r(s[r * 33 + c + 3]);
    *(float4*)(out + (size_t)(n0 + r) * K + k0 + c) = o;
}

// ---------------- LayerNorm (outputs tf32-rounded) --------------------------
__global__ __launch_bounds__(256) void ln_kernel(
    const float* __restrict__ x, const float* __restrict__ scale,
    const float* __restrict__ bias, float* __restrict__ out)
{
    int row = blockIdx.x;
    const float4* xr = (const float4*)(x + (size_t)row * DM);
    float4 v = xr[threadIdx.x];
    float s  = v.x + v.y + v.z + v.w;
    float ss = v.x*v.x + v.y*v.y + v.z*v.z + v.w*v.w;
    #pragma unroll
    for (int o = 16; o > 0; o >>= 1) {
        s  += __shfl_xor_sync(0xffffffffu, s,  o);
        ss += __shfl_xor_sync(0xffffffffu, ss, o);
    }
    __shared__ float smS[8], smSS[8];
    __shared__ float sMean, sRstd;
    int w = threadIdx.x >> 5, lane = threadIdx.x & 31;
    if (lane == 0) { smS[w] = s; smSS[w] = ss; }
    __syncthreads();
    if (threadIdx.x == 0) {
        float S = 0.f, SS = 0.f;
        #pragma unroll
        for (int i = 0; i < 8; i++) { S += smS[i]; SS += smSS[i]; }
        float mean = S * (1.0f / DM);
        float var  = SS * (1.0f / DM) - mean * mean;
        sMean = mean; sRstd = rsqrtf(var + 1e-6f);
    }
    __syncthreads();
    float mean = sMean, rstd = sRstd;
    int c = threadIdx.x * 4;
    float4 sc = *(const float4*)(scale + c);
    float4 bi = *(const float4*)(bias  + c);
    float4 o;
    o.x = tf32r((v.x - mean) * rstd * sc.x + bi.x);
    o.y = tf32r((v.y - mean) * rstd * sc.y + bi.y);
    o.z = tf32r((v.z - mean) * rstd * sc.z + bi.z);
    o.w = tf32r((v.w - mean) * rstd * sc.w + bi.w);
    ((float4*)(out + (size_t)row * DM))[threadIdx.x] = o;
}

// ---------------- TF32 mma.sync GEMM with cp.async pipeline -----------------
#define SK    20
#define NSTG  3
#define STGF  (256 * SK)
#define GSM_BYTES (NSTG * STGF * 4)

__global__ __launch_bounds__(256, 2) void gemm_tf32(
    const float* __restrict__ A, const float* __restrict__ Bt,
    const float* __restrict__ bias, const float* __restrict__ R,
    float* __restrict__ C, int M, int N, int K, int epi)
{
    extern __shared__ float sm[];
    const uint32_t sb = smem_u32(sm);

    const int t  = threadIdx.x;
    const int m0 = blockIdx.y * 128, n0 = blockIdx.x * 128;
    const int w  = t >> 5, lane = t & 31;
    const int wr = w >> 2, wc = w & 3;
    const int wm = wr * 64, wn = wc * 32;
    const int lr = lane >> 2, lc = lane & 3;

    float c[4][4][4];
    #pragma unroll
    for (int mf = 0; mf < 4; mf++)
        #pragma unroll
        for (int nf = 0; nf < 4; nf++)
            #pragma unroll
            for (int i = 0; i < 4; i++) c[mf][nf][i] = 0.f;

    const int grow = t >> 2;
    const int gkc  = (t & 3) * 4;
    const float* Ap0 = A  + (size_t)(m0 + grow)      * K + gkc;
    const float* Ap1 = A  + (size_t)(m0 + 64 + grow) * K + gkc;
    const float* Bp0 = Bt + (size_t)(n0 + grow)      * K + gkc;
    const float* Bp1 = Bt + (size_t)(n0 + 64 + grow) * K + gkc;
    const uint32_t dA0 = sb + (grow * SK + gkc) * 4;
    const uint32_t dA1 = sb + ((grow + 64) * SK + gkc) * 4;
    const uint32_t dB0 = sb + ((128 + grow) * SK + gkc) * 4;
    const uint32_t dB1 = sb + ((128 + 64 + grow) * SK + gkc) * 4;

    const int NC = K >> 4;

    #define LOAD_STAGE(st, cc) do {                                   \
        uint32_t so_ = (uint32_t)(st) * (STGF * 4);                   \
        size_t ko_ = (size_t)(cc) << 4;                               \
        cpa16(dA0 + so_, Ap0 + ko_);                                  \
        cpa16(dA1 + so_, Ap1 + ko_);                                  \
        cpa16(dB0 + so_, Bp0 + ko_);                                  \
        cpa16(dB1 + so_, Bp1 + ko_);                                  \
        CP_COMMIT();                                                  \
    } while (0)

    LOAD_STAGE(0, 0);
    LOAD_STAGE(1, 1);

    int st = 0;
    for (int cc = 0; cc < NC; cc++) {
        CP_WAIT(1);
        __syncthreads();

        const float* as = sm + st * STGF;
        const float* bs = as + 128 * SK;
        #pragma unroll
        for (int ks = 0; ks < 16; ks += 8) {
            float a[4][4], b[4][2];
            #pragma unroll
            for (int mf = 0; mf < 4; mf++) {
                int mr = wm + mf * 16 + lr;
                a[mf][0] = as[mr * SK + ks + lc];
                a[mf][1] = as[(mr + 8) * SK + ks + lc];
                a[mf][2] = as[mr * SK + ks + lc + 4];
                a[mf][3] = as[(mr + 8) * SK + ks + lc + 4];
            }
            #pragma unroll
            for (int nf = 0; nf < 4; nf++) {
                int nr = wn + nf * 8 + lr;
                b[nf][0] = bs[nr * SK + ks + lc];
                b[nf][1] = bs[nr * SK + ks + lc + 4];
            }
            #pragma unroll
            for (int mf = 0; mf < 4; mf++)
                #pragma unroll
                for (int nf = 0; nf < 4; nf++)
                    MMA_TF32(c[mf][nf], a[mf][0], a[mf][1], a[mf][2], a[mf][3],
                             b[nf][0], b[nf][1]);
        }
        __syncthreads();
        if (cc + 2 < NC) LOAD_STAGE((st + 2) % NSTG, cc + 2);
        else             CP_COMMIT();
        st = (st + 1) % NSTG;
    }
    #undef LOAD_STAGE

    #pragma unroll
    for (int mf = 0; mf < 4; mf++) {
        #pragma unroll
        for (int nf = 0; nf < 4; nf++) {
            int row = m0 + wm + mf * 16 + lr;
            int col = n0 + wn + nf * 8 + lc * 2;
            float b0 = bias[col], b1 = bias[col + 1];
            float v0 = c[mf][nf][0] + b0;
            float v1 = c[mf][nf][1] + b1;
            float v2 = c[mf][nf][2] + b0;
            float v3 = c[mf][nf][3] + b1;
            if (epi == 1) {
                const float* r0 = R + (size_t)row * N + col;
                const float* r1 = R + (size_t)(row + 8) * N + col;
                v0 += r0[0]; v1 += r0[1];
                v2 += r1[0]; v3 += r1[1];
            } else if (epi == 2) {
                v0 = tf32r(gelu_f(v0)); v1 = tf32r(gelu_f(v1));
                v2 = tf32r(gelu_f(v2)); v3 = tf32r(gelu_f(v3));
            }
            *(float2*)(C + (size_t)row * N + col)       = make_float2(v0, v1);
            *(float2*)(C + (size_t)(row + 8) * N + col) = make_float2(v2, v3);
        }
    }
}

// ---------------- Flash-attention with mma.sync (tf32, causal) --------------
// BQ=128, BK=64, 8 warps (16 q-rows each).  grid (SEQ/128, BATCH*NHEAD).
#define AS 68
#define ATTN_SM_FLOATS (128*AS + 64*AS + 64*AS + 128*AS)   /* 26112 */
#define ATTN_SM_BYTES  (ATTN_SM_FLOATS * 4)                /* 104448 */

__global__ __launch_bounds__(256) void attn_mma()
{
    extern __shared__ float sm[];
    float* Qs = sm;                  // [128][AS]  q x d, scaled
    float* Ks = Qs + 128 * AS;       // [64][AS]   kseq x d
    float* Vn = Ks + 64 * AS;        // [64][AS]   kseq x d (natural)
    float* Ps = Vn + 64 * AS;        // [128][AS]  q x kseq (per-warp slices)

    const int t = threadIdx.x, w = t >> 5, lane = t & 31;
    const int lr = lane >> 2, lc = lane & 3;
    const int qt = blockIdx.x, bh = blockIdx.y;
    const int b = bh >> 4, h = bh & 15;
    const size_t baseBH = (size_t)b * SEQ * (3 * DM) + (size_t)h * HD;
    const int q0 = qt * 128;
    const int wm = w * 16;

    // load Q (scaled 1/8, tf32-rounded)
    for (int i = t; i < 128 * 16; i += 256) {
        int r = i >> 4, c4 = (i & 15) * 4;
        float4 v = *(const float4*)&g_qkv[baseBH + (size_t)(q0 + r) * (3 * DM) + c4];
        float* q = &Qs[r * AS + c4];
        q[0] = tf32r(v.x * 0.125f); q[1] = tf32r(v.y * 0.125f);
        q[2] = tf32r(v.z * 0.125f); q[3] = tf32r(v.w * 0.125f);
    }

    float o[8][4];
    #pragma unroll
    for (int nf = 0; nf < 8; nf++)
        #pragma unroll
        for (int i = 0; i < 4; i++) o[nf][i] = 0.f;
    float m0v = -1e30f, m1v = -1e30f, l0 = 0.f, l1 = 0.f;

    const int ntile = (q0 + 128) / 64;
    for (int kt = 0; kt < ntile; kt++) {
        int k0 = kt * 64;
        // load K and V tiles (natural layout, tf32-rounded)
        for (int i = t; i < 64 * 16; i += 256) {
            int r = i >> 4, c4 = (i & 15) * 4;
            size_t base = baseBH + (size_t)(k0 + r) * (3 * DM);
            float4 kv = *(const float4*)&g_qkv[base + DM + c4];
            float* kk = &Ks[r * AS + c4];
            kk[0] = tf32r(kv.x); kk[1] = tf32r(kv.y);
            kk[2] = tf32r(kv.z); kk[3] = tf32r(kv.w);
            float4 vv = *(const float4*)&g_qkv[base + 2 * DM + c4];
            float* vp = &Vn[r * AS + c4];
            vp[0] = tf32r(vv.x); vp[1] = tf32r(vv.y);
            vp[2] = tf32r(vv.z); vp[3] = tf32r(vv.w);
        }
        __syncthreads();

        // ---- S = Q @ K^T  (warp: 16 q-rows x 64 k-cols) ----
        float s[8][4];
        #pragma unroll
        for (int nf = 0; nf < 8; nf++)
            #pragma unroll
            for (int i = 0; i < 4; i++) s[nf][i] = 0.f;
        #pragma unroll
        for (int ks = 0; ks < 8; ks++) {
            float a0 = Qs[(wm + lr) * AS + ks * 8 + lc];
            float a1 = Qs[(wm + lr + 8) * AS + ks * 8 + lc];
            float a2 = Qs[(wm + lr) * AS + ks * 8 + lc + 4];
            float a3 = Qs[(wm + lr + 8) * AS + ks * 8 + lc + 4];
            #pragma unroll
            for (int nf = 0; nf < 8; nf++) {
                float b0 = Ks[(nf * 8 + lr) * AS + ks * 8 + lc];
                float b1 = Ks[(nf * 8 + lr) * AS + ks * 8 + lc + 4];
                MMA_TF32(s[nf], a0, a1, a2, a3, b0, b1);
            }
        }

        // ---- causal mask ----
        if (k0 + 63 > q0 + wm) {
            int qi0 = q0 + wm + lr, qi1 = qi0 + 8;
            #pragma unroll
            for (int nf = 0; nf < 8; nf++) {
                int kj0 = k0 + nf * 8 + 2 * lc, kj1 = kj0 + 1;
                if (kj0 > qi0) s[nf][0] = -1e30f;
                if (kj1 > qi0) s[nf][1] = -1e30f;
                if (kj0 > qi1) s[nf][2] = -1e30f;
                if (kj1 > qi1) s[nf][3] = -1e30f;
            }
        }

        // ---- online softmax in registers (rows lr, lr+8; 4 lanes/row) ----
        float mt0 = -1e30f, mt1 = -1e30f;
        #pragma unroll
        for (int nf = 0; nf < 8; nf++) {
            mt0 = fmaxf(mt0, fmaxf(s[nf][0], s[nf][1]));
            mt1 = fmaxf(mt1, fmaxf(s[nf][2], s[nf][3]));
        }
        mt0 = fmaxf(mt0, __shfl_xor_sync(0xffffffffu, mt0, 1));
        mt0 = fmaxf(mt0, __shfl_xor_sync(0xffffffffu, mt0, 2));
        mt1 = fmaxf(mt1, __shfl_xor_sync(0xffffffffu, mt1, 1));
        mt1 = fmaxf(mt1, __shfl_xor_sync(0xffffffffu, mt1, 2));
        float mn0 = fmaxf(m0v, mt0), mn1 = fmaxf(m1v, mt1);
        float scl0 = __expf(m0v - mn0), scl1 = __expf(m1v - mn1);
        m0v = mn0; m1v = mn1;
        float ls0 = 0.f, ls1 = 0.f;
        #pragma unroll
        for (int nf = 0; nf < 8; nf++) {
            float p0 = __expf(s[nf][0] - mn0);
            float p1 = __expf(s[nf][1] - mn0);
            float p2 = __expf(s[nf][2] - mn1);
            float p3 = __expf(s[nf][3] - mn1);
            s[nf][0] = p0; s[nf][1] = p1; s[nf][2] = p2; s[nf][3] = p3;
            ls0 += p0 + p1; ls1 += p2 + p3;
        }
        ls0 += __shfl_xor_sync(0xffffffffu, ls0, 1);
        ls0 += __shfl_xor_sync(0xffffffffu, ls0, 2);
        ls1 += __shfl_xor_sync(0xffffffffu, ls1, 1);
        ls1 += __shfl_xor_sync(0xffffffffu, ls1, 2);
        l0 = l0 * scl0 + ls0;
        l1 = l1 * scl1 + ls1;
        #pragma unroll
        for (int nf = 0; nf < 8; nf++) {
            o[nf][0] *= scl0; o[nf][1] *= scl0;
            o[nf][2] *= scl1; o[nf][3] *= scl1;
        }

        // ---- P -> smem (per-warp slice), then O += P @ V ----
        #pragma unroll
        for (int nf = 0; nf < 8; nf++) {
            Ps[(wm + lr) * AS + nf * 8 + 2 * lc]     = tf32r(s[nf][0]);
            Ps[(wm + lr) * AS + nf * 8 + 2 * lc + 1] = tf32r(s[nf][1]);
            Ps[(wm + lr + 8) * AS + nf * 8 + 2 * lc]     = tf32r(s[nf][2]);
            Ps[(wm + lr + 8) * AS + nf * 8 + 2 * lc + 1] = tf32r(s[nf][3]);
        }
        __syncwarp();

        #pragma unroll
        for (int ks = 0; ks < 8; ks++) {
            float a0 = Ps[(wm + lr) * AS + ks * 8 + lc];
            float a1 = Ps[(wm + lr + 8) * AS + ks * 8 + lc];
            float a2 = Ps[(wm + lr) * AS + ks * 8 + lc + 4];
            float a3 = Ps[(wm + lr + 8) * AS + ks * 8 + lc + 4];
            #pragma unroll
            for (int nf = 0; nf < 8; nf++) {
                float b0 = Vn[(ks * 8 + lc) * AS + nf * 8 + lr];
                float b1 = Vn[(ks * 8 + lc + 4) * AS + nf * 8 + lr];
                MMA_TF32(o[nf], a0, a1, a2, a3, b0, b1);
            }
        }
        __syncthreads();
    }

    // ---- epilogue: O / l, write head-concat layout, tf32-rounded ----
    float il0 = 1.0f / l0, il1 = 1.0f / l1;
    int row0 = q0 + wm + lr, row1 = row0 + 8;
    #pragma unroll
    for (int nf = 0; nf < 8; nf++) {
        int col = h * HD + nf * 8 + 2 * lc;
        *(float2*)&g_attn[(size_t)(b * SEQ + row0) * DM + col] =
            make_float2(tf32r(o[nf][0] * il0), tf32r(o[nf][1] * il0));
        *(float2*)&g_attn[(size_t)(b * SEQ + row1) * DM + col] =
            make_float2(tf32r(o[nf][2] * il1), tf32r(o[nf][3] * il1));
    }
}

// ---------------- launch ---------------------------------------------------
extern "C" void kernel_launch(void* const* d_in, const int* in_sizes, int n_in,
                              void* d_out, int out_size)
{
    (void)in_sizes; (void)n_in; (void)out_size;
    const float* x     = (const float*)d_in[0];
    const float* w_qkv = (const float*)d_in[1];
    const float* b_qkv = (const float*)d_in[2];
    const float* w_out = (const float*)d_in[3];
    const float* b_out = (const float*)d_in[4];
    const float* w_fc1 = (const float*)d_in[5];
    const float* b_fc1 = (const float*)d_in[6];
    const float* w_fc2 = (const float*)d_in[7];
    const float* b_fc2 = (const float*)d_in[8];
    const float* ln1s  = (const float*)d_in[9];
    const float* ln1b  = (const float*)d_in[10];
    const float* ln2s  = (const float*)d_in[11];
    const float* ln2b  = (const float*)d_in[12];
    float* out = (float*)d_out;

    float *xn, *qkv, *attn, *res1, *ff, *wqkvT, *woutT, *wfc1T, *wfc2T;
    cudaGetSymbolAddress((void**)&xn,    g_xn);
    cudaGetSymbolAddress((void**)&qkv,   g_qkv);
    cudaGetSymbolAddress((void**)&attn,  g_attn);
    cudaGetSymbolAddress((void**)&res1,  g_res1);
    cudaGetSymbolAddress((void**)&ff,    g_ff);
    cudaGetSymbolAddress((void**)&wqkvT, g_wqkvT);
    cudaGetSymbolAddress((void**)&woutT, g_woutT);
    cudaGetSymbolAddress((void**)&wfc1T, g_wfc1T);
    cudaGetSymbolAddress((void**)&wfc2T, g_wfc2T);

    cudaFuncSetAttribute(gemm_tf32,
        cudaFuncAttributeMaxDynamicSharedMemorySize, GSM_BYTES);
    cudaFuncSetAttribute(attn_mma,
        cudaFuncAttributeMaxDynamicSharedMemorySize, ATTN_SM_BYTES);

    // 0. weight transposes (tf32-rounded, K-contiguous)
    transpose_rna<<<dim3(3 * DM / 32, DM / 32), 256>>>(w_qkv, wqkvT, DM, 3 * DM);
    transpose_rna<<<dim3(DM / 32, DM / 32), 256>>>(w_out, woutT, DM, DM);
    transpose_rna<<<dim3(DFF / 32, DM / 32), 256>>>(w_fc1, wfc1T, DM, DFF);
    transpose_rna<<<dim3(DM / 32, DFF / 32), 256>>>(w_fc2, wfc2T, DFF, DM);

    // 1. LN1
    ln_kernel<<<NROWS, 256>>>(x, ln1s, ln1b, xn);
    // 2. QKV projection
    gemm_tf32<<<dim3(3 * DM / 128, NROWS / 128), 256, GSM_BYTES>>>(
        xn, wqkvT, b_qkv, (const float*)0, qkv, NROWS, 3 * DM, DM, 0);
    // 3. causal flash attention (tensor cores)
    attn_mma<<<dim3(SEQ / 128, BATCH * NHEAD), 256, ATTN_SM_BYTES>>>();
    // 4. out projection + residual(x)
    gemm_tf32<<<dim3(DM / 128, NROWS / 128), 256, GSM_BYTES>>>(
        attn, woutT, b_out, x, res1, NROWS, DM, DM, 1);
    // 5. LN2
    ln_kernel<<<NROWS, 256>>>(res1, ln2s, ln2b, xn);
    // 6. FC1 + gelu
    gemm_tf32<<<dim3(DFF / 128, NROWS / 128), 256, GSM_BYTES>>>(
        xn, wfc1T, b_fc1, (const float*)0, ff, NROWS, DFF, DM, 2);
    // 7. FC2 + residual(res1) -> out
    gemm_tf32<<<dim3(DM / 128, NROWS / 128), 256, GSM_BYTES>>>(
        ff, wfc2T, b_fc2, res1, out, NROWS, DM, DFF, 1);
}

// round 6
// speedup vs baseline: 3.0547x; 1.0002x over previous
#include <cuda_runtime.h>
#include <math.h>
#include <stdint.h>

#define BATCH 4
#define SEQ   2048
#define DM    1024
#define DFF   4096
#define NHEAD 16
#define HD    64
#define NROWS (BATCH*SEQ)   /* 8192 */

// ---------------- scratch (device globals; no allocation allowed) ----------
__device__ float g_xn   [(size_t)NROWS * DM];
__device__ float g_qkv  [(size_t)NROWS * 3 * DM];
__device__ float g_attn [(size_t)NROWS * DM];
__device__ float g_res1 [(size_t)NROWS * DM];
__device__ float g_ff   [(size_t)NROWS * DFF];
// transposed (N-major, K-contig) tf32-rounded weights
__device__ float g_wqkvT[(size_t)3 * DM * DM];
__device__ float g_woutT[(size_t)DM * DM];
__device__ float g_wfc1T[(size_t)DFF * DM];
__device__ float g_wfc2T[(size_t)DM * DFF];

// ---------------- helpers ---------------------------------------------------
__device__ __forceinline__ float tf32r(float x) {
    uint32_t u;
    asm("cvt.rna.tf32.f32 %0, %1;" : "=r"(u) : "f"(x));
    return __uint_as_float(u);
}
__device__ __forceinline__ void cpa16(uint32_t dst, const void* src) {
    asm volatile("cp.async.cg.shared.global [%0], [%1], 16;" :: "r"(dst), "l"(src));
}
#define CP_COMMIT() asm volatile("cp.async.commit_group;" ::: "memory")
#define CP_WAIT(n)  asm volatile("cp.async.wait_group %0;" :: "n"(n) : "memory")

__device__ __forceinline__ uint32_t smem_u32(const void* p) {
    uint32_t a;
    asm("{ .reg .u64 t; cvta.to.shared.u64 t, %1; cvt.u32.u64 %0, t; }" : "=r"(a) : "l"(p));
    return a;
}

__device__ __forceinline__ float gelu_f(float x) {
    float x3 = x * x * x;
    return 0.5f * x * (1.0f + tanhf(0.7978845608028654f * (x + 0.044715f * x3)));
}

#define MMA_TF32(c, a0,a1,a2,a3, b0,b1)                                     \
    asm volatile(                                                           \
        "mma.sync.aligned.m16n8k8.row.col.f32.tf32.tf32.f32 "               \
        "{%0,%1,%2,%3}, {%4,%5,%6,%7}, {%8,%9}, {%0,%1,%2,%3};\n"           \
        : "+f"((c)[0]), "+f"((c)[1]), "+f"((c)[2]), "+f"((c)[3])            \
        : "r"(__float_as_uint(a0)), "r"(__float_as_uint(a1)),               \
          "r"(__float_as_uint(a2)), "r"(__float_as_uint(a3)),               \
          "r"(__float_as_uint(b0)), "r"(__float_as_uint(b1)))

// ---------------- weight transpose + tf32 round -----------------------------
__global__ __launch_bounds__(256) void transpose_rna(
    const float* __restrict__ in, float* __restrict__ out, int K, int N)
{
    __shared__ float s[32 * 33];
    int t = threadIdx.x;
    int n0 = blockIdx.x * 32, k0 = blockIdx.y * 32;
    int r = t >> 3, c = (t & 7) * 4;
    float4 v = *(const float4*)(in + (size_t)(k0 + r) * N + n0 + c);
    s[(c + 0) * 33 + r] = v.x;
    s[(c + 1) * 33 + r] = v.y;
    s[(c + 2) * 33 + r] = v.z;
    s[(c + 3) * 33 + r] = v.w;
    __syncthreads();
    float4 o;
    o.x = tf32r(s[r * 33 + c + 0]);
    o.y = tf32r(s[r * 33 + c + 1]);
    o.z = tf32r(s[r * 33 + c + 2]);
    o.w = tf32r(s[r * 33 + c + 3]);
    *(float4*)(out + (size_t)(n0 + r) * K + k0 + c) = o;
}

// ---------------- LayerNorm (outputs tf32-rounded) --------------------------
__global__ __launch_bounds__(256) void ln_kernel(
    const float* __restrict__ x, const float* __restrict__ scale,
    const float* __restrict__ bias, float* __restrict__ out)
{
    int row = blockIdx.x;
    const float4* xr = (const float4*)(x + (size_t)row * DM);
    float4 v = xr[threadIdx.x];
    float s  = v.x + v.y + v.z + v.w;
    float ss = v.x*v.x + v.y*v.y + v.z*v.z + v.w*v.w;
    #pragma unroll
    for (int o = 16; o > 0; o >>= 1) {
        s  += __shfl_xor_sync(0xffffffffu, s,  o);
        ss += __shfl_xor_sync(0xffffffffu, ss, o);
    }
    __shared__ float smS[8], smSS[8];
    __shared__ float sMean, sRstd;
    int w = threadIdx.x >> 5, lane = threadIdx.x & 31;
    if (lane == 0) { smS[w] = s; smSS[w] = ss; }
    __syncthreads();
    if (threadIdx.x == 0) {
        float S = 0.f, SS = 0.f;
        #pragma unroll
        for (int i = 0; i < 8; i++) { S += smS[i]; SS += smSS[i]; }
        float mean = S * (1.0f / DM);
        float var  = SS * (1.0f / DM) - mean * mean;
        sMean = mean; sRstd = rsqrtf(var + 1e-6f);
    }
    __syncthreads();
    float mean = sMean, rstd = sRstd;
    int c = threadIdx.x * 4;
    float4 sc = *(const float4*)(scale + c);
    float4 bi = *(const float4*)(bias  + c);
    float4 o;
    o.x = tf32r((v.x - mean) * rstd * sc.x + bi.x);
    o.y = tf32r((v.y - mean) * rstd * sc.y + bi.y);
    o.z = tf32r((v.z - mean) * rstd * sc.z + bi.z);
    o.w = tf32r((v.w - mean) * rstd * sc.w + bi.w);
    ((float4*)(out + (size_t)row * DM))[threadIdx.x] = o;
}

// ---------------- TF32 mma.sync GEMM with cp.async pipeline -----------------
#define SK    20
#define NSTG  3
#define STGF  (256 * SK)
#define GSM_BYTES (NSTG * STGF * 4)

__global__ __launch_bounds__(256, 2) void gemm_tf32(
    const float* __restrict__ A, const float* __restrict__ Bt,
    const float* __restrict__ bias, const float* __restrict__ R,
    float* __restrict__ C, int M, int N, int K, int epi)
{
    extern __shared__ float sm[];
    const uint32_t sb = smem_u32(sm);

    const int t  = threadIdx.x;
    const int m0 = blockIdx.y * 128, n0 = blockIdx.x * 128;
    const int w  = t >> 5, lane = t & 31;
    const int wr = w >> 2, wc = w & 3;
    const int wm = wr * 64, wn = wc * 32;
    const int lr = lane >> 2, lc = lane & 3;

    float c[4][4][4];
    #pragma unroll
    for (int mf = 0; mf < 4; mf++)
        #pragma unroll
        for (int nf = 0; nf < 4; nf++)
            #pragma unroll
            for (int i = 0; i < 4; i++) c[mf][nf][i] = 0.f;

    const int grow = t >> 2;
    const int gkc  = (t & 3) * 4;
    const float* Ap0 = A  + (size_t)(m0 + grow)      * K + gkc;
    const float* Ap1 = A  + (size_t)(m0 + 64 + grow) * K + gkc;
    const float* Bp0 = Bt + (size_t)(n0 + grow)      * K + gkc;
    const float* Bp1 = Bt + (size_t)(n0 + 64 + grow) * K + gkc;
    const uint32_t dA0 = sb + (grow * SK + gkc) * 4;
    const uint32_t dA1 = sb + ((grow + 64) * SK + gkc) * 4;
    const uint32_t dB0 = sb + ((128 + grow) * SK + gkc) * 4;
    const uint32_t dB1 = sb + ((128 + 64 + grow) * SK + gkc) * 4;

    const int NC = K >> 4;

    #define LOAD_STAGE(st, cc) do {                                   \
        uint32_t so_ = (uint32_t)(st) * (STGF * 4);                   \
        size_t ko_ = (size_t)(cc) << 4;                               \
        cpa16(dA0 + so_, Ap0 + ko_);                                  \
        cpa16(dA1 + so_, Ap1 + ko_);                                  \
        cpa16(dB0 + so_, Bp0 + ko_);                                  \
        cpa16(dB1 + so_, Bp1 + ko_);                                  \
        CP_COMMIT();                                                  \
    } while (0)

    LOAD_STAGE(0, 0);
    LOAD_STAGE(1, 1);

    int st = 0;
    for (int cc = 0; cc < NC; cc++) {
        CP_WAIT(1);
        __syncthreads();

        const float* as = sm + st * STGF;
        const float* bs = as + 128 * SK;
        #pragma unroll
        for (int ks = 0; ks < 16; ks += 8) {
            float a[4][4], b[4][2];
            #pragma unroll
            for (int mf = 0; mf < 4; mf++) {
                int mr = wm + mf * 16 + lr;
                a[mf][0] = as[mr * SK + ks + lc];
                a[mf][1] = as[(mr + 8) * SK + ks + lc];
                a[mf][2] = as[mr * SK + ks + lc + 4];
                a[mf][3] = as[(mr + 8) * SK + ks + lc + 4];
            }
            #pragma unroll
            for (int nf = 0; nf < 4; nf++) {
                int nr = wn + nf * 8 + lr;
                b[nf][0] = bs[nr * SK + ks + lc];
                b[nf][1] = bs[nr * SK + ks + lc + 4];
            }
            #pragma unroll
            for (int mf = 0; mf < 4; mf++)
                #pragma unroll
                for (int nf = 0; nf < 4; nf++)
                    MMA_TF32(c[mf][nf], a[mf][0], a[mf][1], a[mf][2], a[mf][3],
                             b[nf][0], b[nf][1]);
        }
        __syncthreads();
        if (cc + 2 < NC) LOAD_STAGE((st + 2) % NSTG, cc + 2);
        else             CP_COMMIT();
        st = (st + 1) % NSTG;
    }
    #undef LOAD_STAGE

    #pragma unroll
    for (int mf = 0; mf < 4; mf++) {
        #pragma unroll
        for (int nf = 0; nf < 4; nf++) {
            int row = m0 + wm + mf * 16 + lr;
            int col = n0 + wn + nf * 8 + lc * 2;
            float b0 = bias[col], b1 = bias[col + 1];
            float v0 = c[mf][nf][0] + b0;
            float v1 = c[mf][nf][1] + b1;
            float v2 = c[mf][nf][2] + b0;
            float v3 = c[mf][nf][3] + b1;
            if (epi == 1) {
                const float* r0 = R + (size_t)row * N + col;
                const float* r1 = R + (size_t)(row + 8) * N + col;
                v0 += r0[0]; v1 += r0[1];
                v2 += r1[0]; v3 += r1[1];
            } else if (epi == 2) {
                v0 = tf32r(gelu_f(v0)); v1 = tf32r(gelu_f(v1));
                v2 = tf32r(gelu_f(v2)); v3 = tf32r(gelu_f(v3));
            }
            *(float2*)(C + (size_t)row * N + col)       = make_float2(v0, v1);
            *(float2*)(C + (size_t)(row + 8) * N + col) = make_float2(v2, v3);
        }
    }
}

// ---------------- Flash-attention with mma.sync (tf32, causal) --------------
// BQ=128, BK=64, 8 warps (16 q-rows each).  grid (SEQ/128, BATCH*NHEAD).
#define AS 68
#define ATTN_SM_FLOATS (128*AS + 64*AS + 64*AS + 128*AS)   /* 26112 */
#define ATTN_SM_BYTES  (ATTN_SM_FLOATS * 4)                /* 104448 */

__global__ __launch_bounds__(256) void attn_mma()
{
    extern __shared__ float sm[];
    float* Qs = sm;                  // [128][AS]  q x d, scaled
    float* Ks = Qs + 128 * AS;       // [64][AS]   kseq x d
    float* Vn = Ks + 64 * AS;        // [64][AS]   kseq x d (natural)
    float* Ps = Vn + 64 * AS;        // [128][AS]  q x kseq (per-warp slices)

    const int t = threadIdx.x, w = t >> 5, lane = t & 31;
    const int lr = lane >> 2, lc = lane & 3;
    const int qt = blockIdx.x, bh = blockIdx.y;
    const int b = bh >> 4, h = bh & 15;
    const size_t baseBH = (size_t)b * SEQ * (3 * DM) + (size_t)h * HD;
    const int q0 = qt * 128;
    const int wm = w * 16;

    // load Q (scaled 1/8, tf32-rounded)
    for (int i = t; i < 128 * 16; i += 256) {
        int r = i >> 4, c4 = (i & 15) * 4;
        float4 v = *(const float4*)&g_qkv[baseBH + (size_t)(q0 + r) * (3 * DM) + c4];
        float* q = &Qs[r * AS + c4];
        q[0] = tf32r(v.x * 0.125f); q[1] = tf32r(v.y * 0.125f);
        q[2] = tf32r(v.z * 0.125f); q[3] = tf32r(v.w * 0.125f);
    }

    float o[8][4];
    #pragma unroll
    for (int nf = 0; nf < 8; nf++)
        #pragma unroll
        for (int i = 0; i < 4; i++) o[nf][i] = 0.f;
    float m0v = -1e30f, m1v = -1e30f, l0 = 0.f, l1 = 0.f;

    const int ntile = (q0 + 128) / 64;
    for (int kt = 0; kt < ntile; kt++) {
        int k0 = kt * 64;
        // load K and V tiles (natural layout, tf32-rounded)
        for (int i = t; i < 64 * 16; i += 256) {
            int r = i >> 4, c4 = (i & 15) * 4;
            size_t base = baseBH + (size_t)(k0 + r) * (3 * DM);
            float4 kv = *(const float4*)&g_qkv[base + DM + c4];
            float* kk = &Ks[r * AS + c4];
            kk[0] = tf32r(kv.x); kk[1] = tf32r(kv.y);
            kk[2] = tf32r(kv.z); kk[3] = tf32r(kv.w);
            float4 vv = *(const float4*)&g_qkv[base + 2 * DM + c4];
            float* vp = &Vn[r * AS + c4];
            vp[0] = tf32r(vv.x); vp[1] = tf32r(vv.y);
            vp[2] = tf32r(vv.z); vp[3] = tf32r(vv.w);
        }
        __syncthreads();

        // ---- S = Q @ K^T  (warp: 16 q-rows x 64 k-cols) ----
        float s[8][4];
        #pragma unroll
        for (int nf = 0; nf < 8; nf++)
            #pragma unroll
            for (int i = 0; i < 4; i++) s[nf][i] = 0.f;
        #pragma unroll
        for (int ks = 0; ks < 8; ks++) {
            float a0 = Qs[(wm + lr) * AS + ks * 8 + lc];
            float a1 = Qs[(wm + lr + 8) * AS + ks * 8 + lc];
            float a2 = Qs[(wm + lr) * AS + ks * 8 + lc + 4];
            float a3 = Qs[(wm + lr + 8) * AS + ks * 8 + lc + 4];
            #pragma unroll
            for (int nf = 0; nf < 8; nf++) {
                float b0 = Ks[(nf * 8 + lr) * AS + ks * 8 + lc];
                float b1 = Ks[(nf * 8 + lr) * AS + ks * 8 + lc + 4];
                MMA_TF32(s[nf], a0, a1, a2, a3, b0, b1);
            }
        }

        // ---- causal mask ----
        if (k0 + 63 > q0 + wm) {
            int qi0 = q0 + wm + lr, qi1 = qi0 + 8;
            #pragma unroll
            for (int nf = 0; nf < 8; nf++) {
                int kj0 = k0 + nf * 8 + 2 * lc, kj1 = kj0 + 1;
                if (kj0 > qi0) s[nf][0] = -1e30f;
                if (kj1 > qi0) s[nf][1] = -1e30f;
                if (kj0 > qi1) s[nf][2] = -1e30f;
                if (kj1 > qi1) s[nf][3] = -1e30f;
            }
        }

        // ---- online softmax in registers (rows lr, lr+8; 4 lanes/row) ----
        float mt0 = -1e30f, mt1 = -1e30f;
        #pragma unroll
        for (int nf = 0; nf < 8; nf++) {
            mt0 = fmaxf(mt0, fmaxf(s[nf][0], s[nf][1]));
            mt1 = fmaxf(mt1, fmaxf(s[nf][2], s[nf][3]));
        }
        mt0 = fmaxf(mt0, __shfl_xor_sync(0xffffffffu, mt0, 1));
        mt0 = fmaxf(mt0, __shfl_xor_sync(0xffffffffu, mt0, 2));
        mt1 = fmaxf(mt1, __shfl_xor_sync(0xffffffffu, mt1, 1));
        mt1 = fmaxf(mt1, __shfl_xor_sync(0xffffffffu, mt1, 2));
        float mn0 = fmaxf(m0v, mt0), mn1 = fmaxf(m1v, mt1);
        float scl0 = __expf(m0v - mn0), scl1 = __expf(m1v - mn1);
        m0v = mn0; m1v = mn1;
        float ls0 = 0.f, ls1 = 0.f;
        #pragma unroll
        for (int nf = 0; nf < 8; nf++) {
            float p0 = __expf(s[nf][0] - mn0);
            float p1 = __expf(s[nf][1] - mn0);
            float p2 = __expf(s[nf][2] - mn1);
            float p3 = __expf(s[nf][3] - mn1);
            s[nf][0] = p0; s[nf][1] = p1; s[nf][2] = p2; s[nf][3] = p3;
            ls0 += p0 + p1; ls1 += p2 + p3;
        }
        ls0 += __shfl_xor_sync(0xffffffffu, ls0, 1);
        ls0 += __shfl_xor_sync(0xffffffffu, ls0, 2);
        ls1 += __shfl_xor_sync(0xffffffffu, ls1, 1);
        ls1 += __shfl_xor_sync(0xffffffffu, ls1, 2);
        l0 = l0 * scl0 + ls0;
        l1 = l1 * scl1 + ls1;
        #pragma unroll
        for (int nf = 0; nf < 8; nf++) {
            o[nf][0] *= scl0; o[nf][1] *= scl0;
            o[nf][2] *= scl1; o[nf][3] *= scl1;
        }

        // ---- P -> smem (per-warp slice), then O += P @ V ----
        #pragma unroll
        for (int nf = 0; nf < 8; nf++) {
            Ps[(wm + lr) * AS + nf * 8 + 2 * lc]     = tf32r(s[nf][0]);
            Ps[(wm + lr) * AS + nf * 8 + 2 * lc + 1] = tf32r(s[nf][1]);
            Ps[(wm + lr + 8) * AS + nf * 8 + 2 * lc]     = tf32r(s[nf][2]);
            Ps[(wm + lr + 8) * AS + nf * 8 + 2 * lc + 1] = tf32r(s[nf][3]);
        }
        __syncwarp();

        #pragma unroll
        for (int ks = 0; ks < 8; ks++) {
            float a0 = Ps[(wm + lr) * AS + ks * 8 + lc];
            float a1 = Ps[(wm + lr + 8) * AS + ks * 8 + lc];
            float a2 = Ps[(wm + lr) * AS + ks * 8 + lc + 4];
            float a3 = Ps[(wm + lr + 8) * AS + ks * 8 + lc + 4];
            #pragma unroll
            for (int nf = 0; nf < 8; nf++) {
                float b0 = Vn[(ks * 8 + lc) * AS + nf * 8 + lr];
                float b1 = Vn[(ks * 8 + lc + 4) * AS + nf * 8 + lr];
                MMA_TF32(o[nf], a0, a1, a2, a3, b0, b1);
            }
        }
        __syncthreads();
    }

    // ---- epilogue: O / l, write head-concat layout, tf32-rounded ----
    float il0 = 1.0f / l0, il1 = 1.0f / l1;
    int row0 = q0 + wm + lr, row1 = row0 + 8;
    #pragma unroll
    for (int nf = 0; nf < 8; nf++) {
        int col = h * HD + nf * 8 + 2 * lc;
        *(float2*)&g_attn[(size_t)(b * SEQ + row0) * DM + col] =
            make_float2(tf32r(o[nf][0] * il0), tf32r(o[nf][1] * il0));
        *(float2*)&g_attn[(size_t)(b * SEQ + row1) * DM + col] =
            make_float2(tf32r(o[nf][2] * il1), tf32r(o[nf][3] * il1));
    }
}

// ---------------- launch ---------------------------------------------------
extern "C" void kernel_launch(void* const* d_in, const int* in_sizes, int n_in,
                              void* d_out, int out_size)
{
    (void)in_sizes; (void)n_in; (void)out_size;
    const float* x     = (const float*)d_in[0];
    const float* w_qkv = (const float*)d_in[1];
    const float* b_qkv = (const float*)d_in[2];
    const float* w_out = (const float*)d_in[3];
    const float* b_out = (const float*)d_in[4];
    const float* w_fc1 = (const float*)d_in[5];
    const float* b_fc1 = (const float*)d_in[6];
    const float* w_fc2 = (const float*)d_in[7];
    const float* b_fc2 = (const float*)d_in[8];
    const float* ln1s  = (const float*)d_in[9];
    const float* ln1b  = (const float*)d_in[10];
    const float* ln2s  = (const float*)d_in[11];
    const float* ln2b  = (const float*)d_in[12];
    float* out = (float*)d_out;

    float *xn, *qkv, *attn, *res1, *ff, *wqkvT, *woutT, *wfc1T, *wfc2T;
    cudaGetSymbolAddress((void**)&xn,    g_xn);
    cudaGetSymbolAddress((void**)&qkv,   g_qkv);
    cudaGetSymbolAddress((void**)&attn,  g_attn);
    cudaGetSymbolAddress((void**)&res1,  g_res1);
    cudaGetSymbolAddress((void**)&ff,    g_ff);
    cudaGetSymbolAddress((void**)&wqkvT, g_wqkvT);
    cudaGetSymbolAddress((void**)&woutT, g_woutT);
    cudaGetSymbolAddress((void**)&wfc1T, g_wfc1T);
    cudaGetSymbolAddress((void**)&wfc2T, g_wfc2T);

    cudaFuncSetAttribute(gemm_tf32,
        cudaFuncAttributeMaxDynamicSharedMemorySize, GSM_BYTES);
    cudaFuncSetAttribute(attn_mma,
        cudaFuncAttributeMaxDynamicSharedMemorySize, ATTN_SM_BYTES);

    // 0. weight transposes (tf32-rounded, K-contiguous)
    transpose_rna<<<dim3(3 * DM / 32, DM / 32), 256>>>(w_qkv, wqkvT, DM, 3 * DM);
    transpose_rna<<<dim3(DM / 32, DM / 32), 256>>>(w_out, woutT, DM, DM);
    transpose_rna<<<dim3(DFF / 32, DM / 32), 256>>>(w_fc1, wfc1T, DM, DFF);
    transpose_rna<<<dim3(DM / 32, DFF / 32), 256>>>(w_fc2, wfc2T, DFF, DM);

    // 1. LN1
    ln_kernel<<<NROWS, 256>>>(x, ln1s, ln1b, xn);
    // 2. QKV projection
    gemm_tf32<<<dim3(3 * DM / 128, NROWS / 128), 256, GSM_BYTES>>>(
        xn, wqkvT, b_qkv, (const float*)0, qkv, NROWS, 3 * DM, DM, 0);
    // 3. causal flash attention (tensor cores)
    attn_mma<<<dim3(SEQ / 128, BATCH * NHEAD), 256, ATTN_SM_BYTES>>>();
    // 4. out projection + residual(x)
    gemm_tf32<<<dim3(DM / 128, NROWS / 128), 256, GSM_BYTES>>>(
        attn, woutT, b_out, x, res1, NROWS, DM, DM, 1);
    // 5. LN2
    ln_kernel<<<NROWS, 256>>>(res1, ln2s, ln2b, xn);
    // 6. FC1 + gelu
    gemm_tf32<<<dim3(DFF / 128, NROWS / 128), 256, GSM_BYTES>>>(
        xn, wfc1T, b_fc1, (const float*)0, ff, NROWS, DFF, DM, 2);
    // 7. FC2 + residual(res1) -> out
    gemm_tf32<<<dim3(DM / 128, NROWS / 128), 256, GSM_BYTES>>>(
        ff, wfc2T, b_fc2, res1, out, NROWS, DM, DFF, 1);
}

// round 7
// speedup vs baseline: 3.0603x; 1.0019x over previous
#include <cuda_runtime.h>
#include <math.h>
#include <stdint.h>

#define BATCH 4
#define SEQ   2048
#define DM    1024
#define DFF   4096
#define NHEAD 16
#define HD    64
#define NROWS (BATCH*SEQ)   /* 8192 */

// ---------------- scratch (device globals; no allocation allowed) ----------
__device__ float g_xn   [(size_t)NROWS * DM];
__device__ float g_qkv  [(size_t)NROWS * 3 * DM];
__device__ float g_attn [(size_t)NROWS * DM];
__device__ float g_res1 [(size_t)NROWS * DM];
__device__ float g_ff   [(size_t)NROWS * DFF];
// transposed (N-major, K-contig) tf32-rounded weights
__device__ float g_wqkvT[(size_t)3 * DM * DM];
__device__ float g_woutT[(size_t)DM * DM];
__device__ float g_wfc1T[(size_t)DFF * DM];
__device__ float g_wfc2T[(size_t)DM * DFF];

// ---------------- helpers ---------------------------------------------------
__device__ __forceinline__ float tf32r(float x) {
    uint32_t u;
    asm("cvt.rna.tf32.f32 %0, %1;" : "=r"(u) : "f"(x));
    return __uint_as_float(u);
}
__device__ __forceinline__ void cpa16(uint32_t dst, const void* src) {
    asm volatile("cp.async.cg.shared.global [%0], [%1], 16;" :: "r"(dst), "l"(src));
}
#define CP_COMMIT() asm volatile("cp.async.commit_group;" ::: "memory")
#define CP_WAIT(n)  asm volatile("cp.async.wait_group %0;" :: "n"(n) : "memory")

__device__ __forceinline__ uint32_t smem_u32(const void* p) {
    uint32_t a;
    asm("{ .reg .u64 t; cvta.to.shared.u64 t, %1; cvt.u32.u64 %0, t; }" : "=r"(a) : "l"(p));
    return a;
}

__device__ __forceinline__ float gelu_f(float x) {
    float x3 = x * x * x;
    return 0.5f * x * (1.0f + tanhf(0.7978845608028654f * (x + 0.044715f * x3)));
}

#define MMA_TF32(c, a0,a1,a2,a3, b0,b1)                                     \
    asm volatile(                                                           \
        "mma.sync.aligned.m16n8k8.row.col.f32.tf32.tf32.f32 "               \
        "{%0,%1,%2,%3}, {%4,%5,%6,%7}, {%8,%9}, {%0,%1,%2,%3};\n"           \
        : "+f"((c)[0]), "+f"((c)[1]), "+f"((c)[2]), "+f"((c)[3])            \
        : "r"(__float_as_uint(a0)), "r"(__float_as_uint(a1)),               \
          "r"(__float_as_uint(a2)), "r"(__float_as_uint(a3)),               \
          "r"(__float_as_uint(b0)), "r"(__float_as_uint(b1)))

// ---------------- weight transpose + tf32 round -----------------------------
__global__ __launch_bounds__(256) void transpose_rna(
    const float* __restrict__ in, float* __restrict__ out, int K, int N)
{
    __shared__ float s[32 * 33];
    int t = threadIdx.x;
    int n0 = blockIdx.x * 32, k0 = blockIdx.y * 32;
    int r = t >> 3, c = (t & 7) * 4;
    float4 v = *(const float4*)(in + (size_t)(k0 + r) * N + n0 + c);
    s[(c + 0) * 33 + r] = v.x;
    s[(c + 1) * 33 + r] = v.y;
    s[(c + 2) * 33 + r] = v.z;
    s[(c + 3) * 33 + r] = v.w;
    __syncthreads();
    float4 o;
    o.x = tf32r(s[r * 33 + c + 0]);
    o.y = tf32r(s[r * 33 + c + 1]);
    o.z = tf32r(s[r * 33 + c + 2]);
    o.w = tf32r(s[r * 33 + c + 3]);
    *(float4*)(out + (size_t)(n0 + r) * K + k0 + c) = o;
}

// ---------------- LayerNorm (outputs tf32-rounded) --------------------------
__global__ __launch_bounds__(256) void ln_kernel(
    const float* __restrict__ x, const float* __restrict__ scale,
    const float* __restrict__ bias, float* __restrict__ out)
{
    int row = blockIdx.x;
    const float4* xr = (const float4*)(x + (size_t)row * DM);
    float4 v = xr[threadIdx.x];
    float s  = v.x + v.y + v.z + v.w;
    float ss = v.x*v.x + v.y*v.y + v.z*v.z + v.w*v.w;
    #pragma unroll
    for (int o = 16; o > 0; o >>= 1) {
        s  += __shfl_xor_sync(0xffffffffu, s,  o);
        ss += __shfl_xor_sync(0xffffffffu, ss, o);
    }
    __shared__ float smS[8], smSS[8];
    __shared__ float sMean, sRstd;
    int w = threadIdx.x >> 5, lane = threadIdx.x & 31;
    if (lane == 0) { smS[w] = s; smSS[w] = ss; }
    __syncthreads();
    if (threadIdx.x == 0) {
        float S = 0.f, SS = 0.f;
        #pragma unroll
        for (int i = 0; i < 8; i++) { S += smS[i]; SS += smSS[i]; }
        float mean = S * (1.0f / DM);
        float var  = SS * (1.0f / DM) - mean * mean;
        sMean = mean; sRstd = rsqrtf(var + 1e-6f);
    }
    __syncthreads();
    float mean = sMean, rstd = sRstd;
    int c = threadIdx.x * 4;
    float4 sc = *(const float4*)(scale + c);
    float4 bi = *(const float4*)(bias  + c);
    float4 o;
    o.x = tf32r((v.x - mean) * rstd * sc.x + bi.x);
    o.y = tf32r((v.y - mean) * rstd * sc.y + bi.y);
    o.z = tf32r((v.z - mean) * rstd * sc.z + bi.z);
    o.w = tf32r((v.w - mean) * rstd * sc.w + bi.w);
    ((float4*)(out + (size_t)row * DM))[threadIdx.x] = o;
}

// ---------------- TF32 mma.sync GEMM with cp.async pipeline -----------------
#define SK    20
#define NSTG  3
#define STGF  (256 * SK)
#define GSM_BYTES (NSTG * STGF * 4)

__global__ __launch_bounds__(256, 2) void gemm_tf32(
    const float* __restrict__ A, const float* __restrict__ Bt,
    const float* __restrict__ bias, const float* __restrict__ R,
    float* __restrict__ C, int M, int N, int K, int epi)
{
    extern __shared__ float sm[];
    const uint32_t sb = smem_u32(sm);

    const int t  = threadIdx.x;
    const int m0 = blockIdx.y * 128, n0 = blockIdx.x * 128;
    const int w  = t >> 5, lane = t & 31;
    const int wr = w >> 2, wc = w & 3;
    const int wm = wr * 64, wn = wc * 32;
    const int lr = lane >> 2, lc = lane & 3;

    float c[4][4][4];
    #pragma unroll
    for (int mf = 0; mf < 4; mf++)
        #pragma unroll
        for (int nf = 0; nf < 4; nf++)
            #pragma unroll
            for (int i = 0; i < 4; i++) c[mf][nf][i] = 0.f;

    const int grow = t >> 2;
    const int gkc  = (t & 3) * 4;
    const float* Ap0 = A  + (size_t)(m0 + grow)      * K + gkc;
    const float* Ap1 = A  + (size_t)(m0 + 64 + grow) * K + gkc;
    const float* Bp0 = Bt + (size_t)(n0 + grow)      * K + gkc;
    const float* Bp1 = Bt + (size_t)(n0 + 64 + grow) * K + gkc;
    const uint32_t dA0 = sb + (grow * SK + gkc) * 4;
    const uint32_t dA1 = sb + ((grow + 64) * SK + gkc) * 4;
    const uint32_t dB0 = sb + ((128 + grow) * SK + gkc) * 4;
    const uint32_t dB1 = sb + ((128 + 64 + grow) * SK + gkc) * 4;

    const int NC = K >> 4;

    #define LOAD_STAGE(st, cc) do {                                   \
        uint32_t so_ = (uint32_t)(st) * (STGF * 4);                   \
        size_t ko_ = (size_t)(cc) << 4;                               \
        cpa16(dA0 + so_, Ap0 + ko_);                                  \
        cpa16(dA1 + so_, Ap1 + ko_);                                  \
        cpa16(dB0 + so_, Bp0 + ko_);                                  \
        cpa16(dB1 + so_, Bp1 + ko_);                                  \
        CP_COMMIT();                                                  \
    } while (0)

    LOAD_STAGE(0, 0);
    LOAD_STAGE(1, 1);

    int st = 0;
    for (int cc = 0; cc < NC; cc++) {
        CP_WAIT(1);
        __syncthreads();

        const float* as = sm + st * STGF;
        const float* bs = as + 128 * SK;
        #pragma unroll
        for (int ks = 0; ks < 16; ks += 8) {
            float a[4][4], b[4][2];
            #pragma unroll
            for (int mf = 0; mf < 4; mf++) {
                int mr = wm + mf * 16 + lr;
                a[mf][0] = as[mr * SK + ks + lc];
                a[mf][1] = as[(mr + 8) * SK + ks + lc];
                a[mf][2] = as[mr * SK + ks + lc + 4];
                a[mf][3] = as[(mr + 8) * SK + ks + lc + 4];
            }
            #pragma unroll
            for (int nf = 0; nf < 4; nf++) {
                int nr = wn + nf * 8 + lr;
                b[nf][0] = bs[nr * SK + ks + lc];
                b[nf][1] = bs[nr * SK + ks + lc + 4];
            }
            #pragma unroll
            for (int mf = 0; mf < 4; mf++)
                #pragma unroll
                for (int nf = 0; nf < 4; nf++)
                    MMA_TF32(c[mf][nf], a[mf][0], a[mf][1], a[mf][2], a[mf][3],
                             b[nf][0], b[nf][1]);
        }
        __syncthreads();
        if (cc + 2 < NC) LOAD_STAGE((st + 2) % NSTG, cc + 2);
        else             CP_COMMIT();
        st = (st + 1) % NSTG;
    }
    #undef LOAD_STAGE

    #pragma unroll
    for (int mf = 0; mf < 4; mf++) {
        #pragma unroll
        for (int nf = 0; nf < 4; nf++) {
            int row = m0 + wm + mf * 16 + lr;
            int col = n0 + wn + nf * 8 + lc * 2;
            float b0 = bias[col], b1 = bias[col + 1];
            float v0 = c[mf][nf][0] + b0;
            float v1 = c[mf][nf][1] + b1;
            float v2 = c[mf][nf][2] + b0;
            float v3 = c[mf][nf][3] + b1;
            if (epi == 1) {
                const float* r0 = R + (size_t)row * N + col;
                const float* r1 = R + (size_t)(row + 8) * N + col;
                v0 += r0[0]; v1 += r0[1];
                v2 += r1[0]; v3 += r1[1];
            } else if (epi == 2) {
                v0 = tf32r(gelu_f(v0)); v1 = tf32r(gelu_f(v1));
                v2 = tf32r(gelu_f(v2)); v3 = tf32r(gelu_f(v3));
            }
            *(float2*)(C + (size_t)row * N + col)       = make_float2(v0, v1);
            *(float2*)(C + (size_t)(row + 8) * N + col) = make_float2(v2, v3);
        }
    }
}

// ---------------- Flash-attention with mma.sync (tf32, causal) --------------
// BQ=128, BK=64, 8 warps (16 q-rows each).  grid (SEQ/128, BATCH*NHEAD).
#define AS 68
#define ATTN_SM_FLOATS (128*AS + 64*AS + 64*AS + 128*AS)   /* 26112 */
#define ATTN_SM_BYTES  (ATTN_SM_FLOATS * 4)                /* 104448 */

__global__ __launch_bounds__(256) void attn_mma()
{
    extern __shared__ float sm[];
    float* Qs = sm;                  // [128][AS]  q x d, scaled
    float* Ks = Qs + 128 * AS;       // [64][AS]   kseq x d
    float* Vn = Ks + 64 * AS;        // [64][AS]   kseq x d (natural)
    float* Ps = Vn + 64 * AS;        // [128][AS]  q x kseq (per-warp slices)

    const int t = threadIdx.x, w = t >> 5, lane = t & 31;
    const int lr = lane >> 2, lc = lane & 3;
    const int qt = blockIdx.x, bh = blockIdx.y;
    const int b = bh >> 4, h = bh & 15;
    const size_t baseBH = (size_t)b * SEQ * (3 * DM) + (size_t)h * HD;
    const int q0 = qt * 128;
    const int wm = w * 16;

    // load Q (scaled 1/8, tf32-rounded)
    for (int i = t; i < 128 * 16; i += 256) {
        int r = i >> 4, c4 = (i & 15) * 4;
        float4 v = *(const float4*)&g_qkv[baseBH + (size_t)(q0 + r) * (3 * DM) + c4];
        float* q = &Qs[r * AS + c4];
        q[0] = tf32r(v.x * 0.125f); q[1] = tf32r(v.y * 0.125f);
        q[2] = tf32r(v.z * 0.125f); q[3] = tf32r(v.w * 0.125f);
    }

    float o[8][4];
    #pragma unroll
    for (int nf = 0; nf < 8; nf++)
        #pragma unroll
        for (int i = 0; i < 4; i++) o[nf][i] = 0.f;
    float m0v = -1e30f, m1v = -1e30f, l0 = 0.f, l1 = 0.f;

    const int ntile = (q0 + 128) / 64;
    for (int kt = 0; kt < ntile; kt++) {
        int k0 = kt * 64;
        // load K and V tiles (natural layout, tf32-rounded)
        for (int i = t; i < 64 * 16; i += 256) {
            int r = i >> 4, c4 = (i & 15) * 4;
            size_t base = baseBH + (size_t)(k0 + r) * (3 * DM);
            float4 kv = *(const float4*)&g_qkv[base + DM + c4];
            float* kk = &Ks[r * AS + c4];
            kk[0] = tf32r(kv.x); kk[1] = tf32r(kv.y);
            kk[2] = tf32r(kv.z); kk[3] = tf32r(kv.w);
            float4 vv = *(const float4*)&g_qkv[base + 2 * DM + c4];
            float* vp = &Vn[r * AS + c4];
            vp[0] = tf32r(vv.x); vp[1] = tf32r(vv.y);
            vp[2] = tf32r(vv.z); vp[3] = tf32r(vv.w);
        }
        __syncthreads();

        // ---- S = Q @ K^T  (warp: 16 q-rows x 64 k-cols) ----
        float s[8][4];
        #pragma unroll
        for (int nf = 0; nf < 8; nf++)
            #pragma unroll
            for (int i = 0; i < 4; i++) s[nf][i] = 0.f;
        #pragma unroll
        for (int ks = 0; ks < 8; ks++) {
            float a0 = Qs[(wm + lr) * AS + ks * 8 + lc];
            float a1 = Qs[(wm + lr + 8) * AS + ks * 8 + lc];
            float a2 = Qs[(wm + lr) * AS + ks * 8 + lc + 4];
            float a3 = Qs[(wm + lr + 8) * AS + ks * 8 + lc + 4];
            #pragma unroll
            for (int nf = 0; nf < 8; nf++) {
                float b0 = Ks[(nf * 8 + lr) * AS + ks * 8 + lc];
                float b1 = Ks[(nf * 8 + lr) * AS + ks * 8 + lc + 4];
                MMA_TF32(s[nf], a0, a1, a2, a3, b0, b1);
            }
        }

        // ---- causal mask ----
        if (k0 + 63 > q0 + wm) {
            int qi0 = q0 + wm + lr, qi1 = qi0 + 8;
            #pragma unroll
            for (int nf = 0; nf < 8; nf++) {
                int kj0 = k0 + nf * 8 + 2 * lc, kj1 = kj0 + 1;
                if (kj0 > qi0) s[nf][0] = -1e30f;
                if (kj1 > qi0) s[nf][1] = -1e30f;
                if (kj0 > qi1) s[nf][2] = -1e30f;
                if (kj1 > qi1) s[nf][3] = -1e30f;
            }
        }

        // ---- online softmax in registers (rows lr, lr+8; 4 lanes/row) ----
        float mt0 = -1e30f, mt1 = -1e30f;
        #pragma unroll
        for (int nf = 0; nf < 8; nf++) {
            mt0 = fmaxf(mt0, fmaxf(s[nf][0], s[nf][1]));
            mt1 = fmaxf(mt1, fmaxf(s[nf][2], s[nf][3]));
        }
        mt0 = fmaxf(mt0, __shfl_xor_sync(0xffffffffu, mt0, 1));
        mt0 = fmaxf(mt0, __shfl_xor_sync(0xffffffffu, mt0, 2));
        mt1 = fmaxf(mt1, __shfl_xor_sync(0xffffffffu, mt1, 1));
        mt1 = fmaxf(mt1, __shfl_xor_sync(0xffffffffu, mt1, 2));
        float mn0 = fmaxf(m0v, mt0), mn1 = fmaxf(m1v, mt1);
        float scl0 = __expf(m0v - mn0), scl1 = __expf(m1v - mn1);
        m0v = mn0; m1v = mn1;
        float ls0 = 0.f, ls1 = 0.f;
        #pragma unroll
        for (int nf = 0; nf < 8; nf++) {
            float p0 = __expf(s[nf][0] - mn0);
            float p1 = __expf(s[nf][1] - mn0);
            float p2 = __expf(s[nf][2] - mn1);
            float p3 = __expf(s[nf][3] - mn1);
            s[nf][0] = p0; s[nf][1] = p1; s[nf][2] = p2; s[nf][3] = p3;
            ls0 += p0 + p1; ls1 += p2 + p3;
        }
        ls0 += __shfl_xor_sync(0xffffffffu, ls0, 1);
        ls0 += __shfl_xor_sync(0xffffffffu, ls0, 2);
        ls1 += __shfl_xor_sync(0xffffffffu, ls1, 1);
        ls1 += __shfl_xor_sync(0xffffffffu, ls1, 2);
        l0 = l0 * scl0 + ls0;
        l1 = l1 * scl1 + ls1;
        #pragma unroll
        for (int nf = 0; nf < 8; nf++) {
            o[nf][0] *= scl0; o[nf][1] *= scl0;
            o[nf][2] *= scl1; o[nf][3] *= scl1;
        }

        // ---- P -> smem (per-warp slice), then O += P @ V ----
        #pragma unroll
        for (int nf = 0; nf < 8; nf++) {
            Ps[(wm + lr) * AS + nf * 8 + 2 * lc]     = tf32r(s[nf][0]);
            Ps[(wm + lr) * AS + nf * 8 + 2 * lc + 1] = tf32r(s[nf][1]);
            Ps[(wm + lr + 8) * AS + nf * 8 + 2 * lc]     = tf32r(s[nf][2]);
            Ps[(wm + lr + 8) * AS + nf * 8 + 2 * lc + 1] = tf32r(s[nf][3]);
        }
        __syncwarp();

        #pragma unroll
        for (int ks = 0; ks < 8; ks++) {
            float a0 = Ps[(wm + lr) * AS + ks * 8 + lc];
            float a1 = Ps[(wm + lr + 8) * AS + ks * 8 + lc];
            float a2 = Ps[(wm + lr) * AS + ks * 8 + lc + 4];
            float a3 = Ps[(wm + lr + 8) * AS + ks * 8 + lc + 4];
            #pragma unroll
            for (int nf = 0; nf < 8; nf++) {
                float b0 = Vn[(ks * 8 + lc) * AS + nf * 8 + lr];
                float b1 = Vn[(ks * 8 + lc + 4) * AS + nf * 8 + lr];
                MMA_TF32(o[nf], a0, a1, a2, a3, b0, b1);
            }
        }
        __syncthreads();
    }

    // ---- epilogue: O / l, write head-concat layout, tf32-rounded ----
    float il0 = 1.0f / l0, il1 = 1.0f / l1;
    int row0 = q0 + wm + lr, row1 = row0 + 8;
    #pragma unroll
    for (int nf = 0; nf < 8; nf++) {
        int col = h * HD + nf * 8 + 2 * lc;
        *(float2*)&g_attn[(size_t)(b * SEQ + row0) * DM + col] =
            make_float2(tf32r(o[nf][0] * il0), tf32r(o[nf][1] * il0));
        *(float2*)&g_attn[(size_t)(b * SEQ + row1) * DM + col] =
            make_float2(tf32r(o[nf][2] * il1), tf32r(o[nf][3] * il1));
    }
}

// ---------------- launch ---------------------------------------------------
extern "C" void kernel_launch(void* const* d_in, const int* in_sizes, int n_in,
                              void* d_out, int out_size)
{
    (void)in_sizes; (void)n_in; (void)out_size;
    const float* x     = (const float*)d_in[0];
    const float* w_qkv = (const float*)d_in[1];
    const float* b_qkv = (const float*)d_in[2];
    const float* w_out = (const float*)d_in[3];
    const float* b_out = (const float*)d_in[4];
    const float* w_fc1 = (const float*)d_in[5];
    const float* b_fc1 = (const float*)d_in[6];
    const float* w_fc2 = (const float*)d_in[7];
    const float* b_fc2 = (const float*)d_in[8];
    const float* ln1s  = (const float*)d_in[9];
    const float* ln1b  = (const float*)d_in[10];
    const float* ln2s  = (const float*)d_in[11];
    const float* ln2b  = (const float*)d_in[12];
    float* out = (float*)d_out;

    float *xn, *qkv, *attn, *res1, *ff, *wqkvT, *woutT, *wfc1T, *wfc2T;
    cudaGetSymbolAddress((void**)&xn,    g_xn);
    cudaGetSymbolAddress((void**)&qkv,   g_qkv);
    cudaGetSymbolAddress((void**)&attn,  g_attn);
    cudaGetSymbolAddress((void**)&res1,  g_res1);
    cudaGetSymbolAddress((void**)&ff,    g_ff);
    cudaGetSymbolAddress((void**)&wqkvT, g_wqkvT);
    cudaGetSymbolAddress((void**)&woutT, g_woutT);
    cudaGetSymbolAddress((void**)&wfc1T, g_wfc1T);
    cudaGetSymbolAddress((void**)&wfc2T, g_wfc2T);

    cudaFuncSetAttribute(gemm_tf32,
        cudaFuncAttributeMaxDynamicSharedMemorySize, GSM_BYTES);
    cudaFuncSetAttribute(attn_mma,
        cudaFuncAttributeMaxDynamicSharedMemorySize, ATTN_SM_BYTES);

    // 0. weight transposes (tf32-rounded, K-contiguous)
    transpose_rna<<<dim3(3 * DM / 32, DM / 32), 256>>>(w_qkv, wqkvT, DM, 3 * DM);
    transpose_rna<<<dim3(DM / 32, DM / 32), 256>>>(w_out, woutT, DM, DM);
    transpose_rna<<<dim3(DFF / 32, DM / 32), 256>>>(w_fc1, wfc1T, DM, DFF);
    transpose_rna<<<dim3(DM / 32, DFF / 32), 256>>>(w_fc2, wfc2T, DFF, DM);

    // 1. LN1
    ln_kernel<<<NROWS, 256>>>(x, ln1s, ln1b, xn);
    // 2. QKV projection
    gemm_tf32<<<dim3(3 * DM / 128, NROWS / 128), 256, GSM_BYTES>>>(
        xn, wqkvT, b_qkv, (const float*)0, qkv, NROWS, 3 * DM, DM, 0);
    // 3. causal flash attention (tensor cores)
    attn_mma<<<dim3(SEQ / 128, BATCH * NHEAD), 256, ATTN_SM_BYTES>>>();
    // 4. out projection + residual(x)
    gemm_tf32<<<dim3(DM / 128, NROWS / 128), 256, GSM_BYTES>>>(
        attn, woutT, b_out, x, res1, NROWS, DM, DM, 1);
    // 5. LN2
    ln_kernel<<<NROWS, 256>>>(res1, ln2s, ln2b, xn);
    // 6. FC1 + gelu
    gemm_tf32<<<dim3(DFF / 128, NROWS / 128), 256, GSM_BYTES>>>(
        xn, wfc1T, b_fc1, (const float*)0, ff, NROWS, DFF, DM, 2);
    // 7. FC2 + residual(res1) -> out
    gemm_tf32<<<dim3(DM / 128, NROWS / 128), 256, GSM_BYTES>>>(
        ff, wfc2T, b_fc2, res1, out, NROWS, DM, DFF, 1);
}

// round 8
// speedup vs baseline: 4.6482x; 1.5189x over previous
#include <cuda_runtime.h>
#include <cuda_fp16.h>
#include <math.h>
#include <stdint.h>

#define BATCH 4
#define SEQ   2048
#define DM    1024
#define DFF   4096
#define NHEAD 16
#define HD    64
#define NROWS (BATCH*SEQ)   /* 8192 */

// ---------------- scratch (device globals; no allocation allowed) ----------
__device__ __half g_xn   [(size_t)NROWS * DM];        // LN out (half)
__device__ float  g_qkv  [(size_t)NROWS * 3 * DM];    // fp32 (attention input)
__device__ __half g_attnh[(size_t)NROWS * DM];        // attention out (half)
__device__ float  g_res1 [(size_t)NROWS * DM];
__device__ __half g_ff   [(size_t)NROWS * DFF];       // gelu out (half)
// transposed (N-major, K-contig) half weights
__device__ __half g_wqkvT[(size_t)3 * DM * DM];
__device__ __half g_woutT[(size_t)DM * DM];
__device__ __half g_wfc1T[(size_t)DFF * DM];
__device__ __half g_wfc2T[(size_t)DM * DFF];

// ---------------- helpers ---------------------------------------------------
__device__ __forceinline__ float tf32r(float x) {
    uint32_t u;
    asm("cvt.rna.tf32.f32 %0, %1;" : "=r"(u) : "f"(x));
    return __uint_as_float(u);
}
__device__ __forceinline__ void cpa16(uint32_t dst, const void* src) {
    asm volatile("cp.async.cg.shared.global [%0], [%1], 16;" :: "r"(dst), "l"(src));
}
#define CP_COMMIT() asm volatile("cp.async.commit_group;" ::: "memory")
#define CP_WAIT(n)  asm volatile("cp.async.wait_group %0;" :: "n"(n) : "memory")

__device__ __forceinline__ uint32_t smem_u32(const void* p) {
    uint32_t a;
    asm("{ .reg .u64 t; cvta.to.shared.u64 t, %1; cvt.u32.u64 %0, t; }" : "=r"(a) : "l"(p));
    return a;
}
__device__ __forceinline__ float gelu_f(float x) {
    float x3 = x * x * x;
    return 0.5f * x * (1.0f + tanhf(0.7978845608028654f * (x + 0.044715f * x3)));
}

#define LDSM4(r0, r1, r2, r3, addr) \
    asm volatile("ldmatrix.sync.aligned.m8n8.x4.shared.b16 {%0,%1,%2,%3}, [%4];" \
        : "=r"(r0), "=r"(r1), "=r"(r2), "=r"(r3) : "r"(addr))

#define MMA_F16(c, a0,a1,a2,a3, b0,b1)                                      \
    asm volatile(                                                           \
        "mma.sync.aligned.m16n8k16.row.col.f32.f16.f16.f32 "                \
        "{%0,%1,%2,%3}, {%4,%5,%6,%7}, {%8,%9}, {%0,%1,%2,%3};\n"           \
        : "+f"((c)[0]), "+f"((c)[1]), "+f"((c)[2]), "+f"((c)[3])            \
        : "r"(a0), "r"(a1), "r"(a2), "r"(a3), "r"(b0), "r"(b1))

#define MMA_TF32(c, a0,a1,a2,a3, b0,b1)                                     \
    asm volatile(                                                           \
        "mma.sync.aligned.m16n8k8.row.col.f32.tf32.tf32.f32 "               \
        "{%0,%1,%2,%3}, {%4,%5,%6,%7}, {%8,%9}, {%0,%1,%2,%3};\n"           \
        : "+f"((c)[0]), "+f"((c)[1]), "+f"((c)[2]), "+f"((c)[3])            \
        : "r"(__float_as_uint(a0)), "r"(__float_as_uint(a1)),               \
          "r"(__float_as_uint(a2)), "r"(__float_as_uint(a3)),               \
          "r"(__float_as_uint(b0)), "r"(__float_as_uint(b1)))

// ---------------- weight transpose -> half, K-contiguous --------------------
__global__ __launch_bounds__(256) void transpose_h(
    const float* __restrict__ in, __half* __restrict__ out, int K, int N)
{
    __shared__ float s[32 * 33];
    int t = threadIdx.x;
    int n0 = blockIdx.x * 32, k0 = blockIdx.y * 32;
    int r = t >> 3, c = (t & 7) * 4;
    float4 v = *(const float4*)(in + (size_t)(k0 + r) * N + n0 + c);
    s[(c + 0) * 33 + r] = v.x;
    s[(c + 1) * 33 + r] = v.y;
    s[(c + 2) * 33 + r] = v.z;
    s[(c + 3) * 33 + r] = v.w;
    __syncthreads();
    __half2 h0 = __floats2half2_rn(s[r * 33 + c + 0], s[r * 33 + c + 1]);
    __half2 h1 = __floats2half2_rn(s[r * 33 + c + 2], s[r * 33 + c + 3]);
    __half* op = out + (size_t)(n0 + r) * K + k0 + c;
    *(__half2*)(op)     = h0;
    *(__half2*)(op + 2) = h1;
}

// ---------------- LayerNorm (outputs half) ----------------------------------
__global__ __launch_bounds__(256) void ln_kernel(
    const float* __restrict__ x, const float* __restrict__ scale,
    const float* __restrict__ bias, __half* __restrict__ out)
{
    int row = blockIdx.x;
    const float4* xr = (const float4*)(x + (size_t)row * DM);
    float4 v = xr[threadIdx.x];
    float s  = v.x + v.y + v.z + v.w;
    float ss = v.x*v.x + v.y*v.y + v.z*v.z + v.w*v.w;
    #pragma unroll
    for (int o = 16; o > 0; o >>= 1) {
        s  += __shfl_xor_sync(0xffffffffu, s,  o);
        ss += __shfl_xor_sync(0xffffffffu, ss, o);
    }
    __shared__ float smS[8], smSS[8];
    __shared__ float sMean, sRstd;
    int w = threadIdx.x >> 5, lane = threadIdx.x & 31;
    if (lane == 0) { smS[w] = s; smSS[w] = ss; }
    __syncthreads();
    if (threadIdx.x == 0) {
        float S = 0.f, SS = 0.f;
        #pragma unroll
        for (int i = 0; i < 8; i++) { S += smS[i]; SS += smSS[i]; }
        float mean = S * (1.0f / DM);
        float var  = SS * (1.0f / DM) - mean * mean;
        sMean = mean; sRstd = rsqrtf(var + 1e-6f);
    }
    __syncthreads();
    float mean = sMean, rstd = sRstd;
    int c = threadIdx.x * 4;
    float4 sc = *(const float4*)(scale + c);
    float4 bi = *(const float4*)(bias  + c);
    __half2 h0 = __floats2half2_rn((v.x - mean) * rstd * sc.x + bi.x,
                                   (v.y - mean) * rstd * sc.y + bi.y);
    __half2 h1 = __floats2half2_rn((v.z - mean) * rstd * sc.z + bi.z,
                                   (v.w - mean) * rstd * sc.w + bi.w);
    __half* op = out + (size_t)row * DM + c;
    *(__half2*)(op)     = h0;
    *(__half2*)(op + 2) = h1;
}

// ---------------- FP16 mma.sync GEMM with ldmatrix + cp.async ---------------
// C[M,N] = A[M,K] @ Bt[N,K]^T + bias (+res / gelu->half).
// Block 128x128, BK=32 halves, 8 warps (2x4), warp tile 64x32, 3 stages.
// smem row = 64B data + 16B pad (stride 80B) -> ldmatrix conflict-free.
#define HROWB 80
#define HSTGB (128 * HROWB * 2)        /* 20480 B per stage (A+B) */
#define HGSM  (3 * HSTGB)              /* 61440 B */

__global__ __launch_bounds__(256, 2) void gemm_f16(
    const __half* __restrict__ A, const __half* __restrict__ Bt,
    const float* __restrict__ bias, const float* __restrict__ R,
    float* __restrict__ C, __half* __restrict__ Ch,
    int M, int N, int K, int epi)
{
    extern __shared__ char smc[];
    const uint32_t sb = smem_u32(smc);

    const int t  = threadIdx.x;
    const int m0 = blockIdx.y * 128, n0 = blockIdx.x * 128;
    const int w  = t >> 5, lane = t & 31;
    const int wr = w >> 2, wc = w & 3;
    const int wm = wr * 64, wn = wc * 32;
    const int lr = lane >> 2, lc = lane & 3;

    float c[4][4][4];
    #pragma unroll
    for (int mf = 0; mf < 4; mf++)
        #pragma unroll
        for (int nf = 0; nf < 4; nf++)
            #pragma unroll
            for (int i = 0; i < 4; i++) c[mf][nf][i] = 0.f;

    // loader: thread -> (row = t>>2 in 0..63, granule kg = t&3); rows row, row+64
    const int row = t >> 2, kg = t & 3;
    const __half* Ap0 = A  + (size_t)(m0 + row)      * K + kg * 8;
    const __half* Ap1 = A  + (size_t)(m0 + 64 + row) * K + kg * 8;
    const __half* Bp0 = Bt + (size_t)(n0 + row)      * K + kg * 8;
    const __half* Bp1 = Bt + (size_t)(n0 + 64 + row) * K + kg * 8;
    const uint32_t dA0 = sb + row * HROWB + kg * 16;
    const uint32_t dA1 = sb + (row + 64) * HROWB + kg * 16;
    const uint32_t dB0 = sb + 10240 + row * HROWB + kg * 16;
    const uint32_t dB1 = sb + 10240 + (row + 64) * HROWB + kg * 16;

    const int NC = K >> 5;              // chunks of 32 halves

    #define LOAD_STAGE(st, cc) do {                                   \
        uint32_t so_ = (uint32_t)(st) * HSTGB;                        \
        size_t ko_ = (size_t)(cc) << 5;                               \
        cpa16(dA0 + so_, Ap0 + ko_);                                  \
        cpa16(dA1 + so_, Ap1 + ko_);                                  \
        cpa16(dB0 + so_, Bp0 + ko_);                                  \
        cpa16(dB1 + so_, Bp1 + ko_);                                  \
        CP_COMMIT();                                                  \
    } while (0)

    LOAD_STAGE(0, 0);
    LOAD_STAGE(1, 1);

    // ldmatrix lane addressing: row-within-16 = lane&15, k-half = (lane>>4)*8
    const int lm_r = lane & 15;
    const int lm_k = (lane >> 4) * 16;   // byte offset: 8 halves = 16B

    int st = 0;
    for (int cc = 0; cc < NC; cc++) {
        CP_WAIT(1);
        __syncthreads();

        const uint32_t as = sb + st * HSTGB;
        const uint32_t bs = as + 10240;
        #pragma unroll
        for (int ks = 0; ks < 2; ks++) {
            uint32_t af[4][4];
            #pragma unroll
            for (int mf = 0; mf < 4; mf++) {
                uint32_t addr = as + (wm + mf * 16 + lm_r) * HROWB + ks * 32 + lm_k;
                LDSM4(af[mf][0], af[mf][1], af[mf][2], af[mf][3], addr);
            }
            uint32_t bf[4][2];
            #pragma unroll
            for (int np = 0; np < 2; np++) {
                uint32_t r0, r1, r2, r3;
                uint32_t addr = bs + (wn + np * 16 + lm_r) * HROWB + ks * 32 + lm_k;
                LDSM4(r0, r1, r2, r3, addr);
                bf[np * 2 + 0][0] = r0; bf[np * 2 + 0][1] = r2;
                bf[np * 2 + 1][0] = r1; bf[np * 2 + 1][1] = r3;
            }
            #pragma unroll
            for (int mf = 0; mf < 4; mf++)
                #pragma unroll
                for (int nf = 0; nf < 4; nf++)
                    MMA_F16(c[mf][nf], af[mf][0], af[mf][1], af[mf][2], af[mf][3],
                            bf[nf][0], bf[nf][1]);
        }
        __syncthreads();
        if (cc + 2 < NC) LOAD_STAGE((st + 2) % 3, cc + 2);
        else             CP_COMMIT();
        st = (st + 1) % 3;
    }
    #undef LOAD_STAGE

    // -------- epilogue --------
    #pragma unroll
    for (int mf = 0; mf < 4; mf++) {
        #pragma unroll
        for (int nf = 0; nf < 4; nf++) {
            int rowg = m0 + wm + mf * 16 + lr;
            int col  = n0 + wn + nf * 8 + lc * 2;
            float b0 = bias[col], b1 = bias[col + 1];
            float v0 = c[mf][nf][0] + b0;
            float v1 = c[mf][nf][1] + b1;
            float v2 = c[mf][nf][2] + b0;
            float v3 = c[mf][nf][3] + b1;
            if (epi == 1) {
                const float* r0 = R + (size_t)rowg * N + col;
                const float* r1 = R + (size_t)(rowg + 8) * N + col;
                v0 += r0[0]; v1 += r0[1];
                v2 += r1[0]; v3 += r1[1];
                *(float2*)(C + (size_t)rowg * N + col)       = make_float2(v0, v1);
                *(float2*)(C + (size_t)(rowg + 8) * N + col) = make_float2(v2, v3);
            } else if (epi == 2) {
                *(__half2*)(Ch + (size_t)rowg * N + col) =
                    __floats2half2_rn(gelu_f(v0), gelu_f(v1));
                *(__half2*)(Ch + (size_t)(rowg + 8) * N + col) =
                    __floats2half2_rn(gelu_f(v2), gelu_f(v3));
            } else {
                *(float2*)(C + (size_t)rowg * N + col)       = make_float2(v0, v1);
                *(float2*)(C + (size_t)(rowg + 8) * N + col) = make_float2(v2, v3);
            }
        }
    }
}

// ---------------- Flash-attention with mma.sync (tf32, causal) --------------
// BQ=128, BK=64, 8 warps (16 q-rows each).  grid (SEQ/128, BATCH*NHEAD).
#define AS 68
#define ATTN_SM_FLOATS (128*AS + 64*AS + 64*AS + 128*AS)
#define ATTN_SM_BYTES  (ATTN_SM_FLOATS * 4)

__global__ __launch_bounds__(256) void attn_mma()
{
    extern __shared__ float sm[];
    float* Qs = sm;
    float* Ks = Qs + 128 * AS;
    float* Vn = Ks + 64 * AS;
    float* Ps = Vn + 64 * AS;

    const int t = threadIdx.x, w = t >> 5, lane = t & 31;
    const int lr = lane >> 2, lc = lane & 3;
    const int qt = blockIdx.x, bh = blockIdx.y;
    const int b = bh >> 4, h = bh & 15;
    const size_t baseBH = (size_t)b * SEQ * (3 * DM) + (size_t)h * HD;
    const int q0 = qt * 128;
    const int wm = w * 16;

    for (int i = t; i < 128 * 16; i += 256) {
        int r = i >> 4, c4 = (i & 15) * 4;
        float4 v = *(const float4*)&g_qkv[baseBH + (size_t)(q0 + r) * (3 * DM) + c4];
        float* q = &Qs[r * AS + c4];
        q[0] = tf32r(v.x * 0.125f); q[1] = tf32r(v.y * 0.125f);
        q[2] = tf32r(v.z * 0.125f); q[3] = tf32r(v.w * 0.125f);
    }

    float o[8][4];
    #pragma unroll
    for (int nf = 0; nf < 8; nf++)
        #pragma unroll
        for (int i = 0; i < 4; i++) o[nf][i] = 0.f;
    float m0v = -1e30f, m1v = -1e30f, l0 = 0.f, l1 = 0.f;

    const int ntile = (q0 + 128) / 64;
    for (int kt = 0; kt < ntile; kt++) {
        int k0 = kt * 64;
        for (int i = t; i < 64 * 16; i += 256) {
            int r = i >> 4, c4 = (i & 15) * 4;
            size_t base = baseBH + (size_t)(k0 + r) * (3 * DM);
            float4 kv = *(const float4*)&g_qkv[base + DM + c4];
            float* kk = &Ks[r * AS + c4];
            kk[0] = tf32r(kv.x); kk[1] = tf32r(kv.y);
            kk[2] = tf32r(kv.z); kk[3] = tf32r(kv.w);
            float4 vv = *(const float4*)&g_qkv[base + 2 * DM + c4];
            float* vp = &Vn[r * AS + c4];
            vp[0] = tf32r(vv.x); vp[1] = tf32r(vv.y);
            vp[2] = tf32r(vv.z); vp[3] = tf32r(vv.w);
        }
        __syncthreads();

        float s[8][4];
        #pragma unroll
        for (int nf = 0; nf < 8; nf++)
            #pragma unroll
            for (int i = 0; i < 4; i++) s[nf][i] = 0.f;
        #pragma unroll
        for (int ks = 0; ks < 8; ks++) {
            float a0 = Qs[(wm + lr) * AS + ks * 8 + lc];
            float a1 = Qs[(wm + lr + 8) * AS + ks * 8 + lc];
            float a2 = Qs[(wm + lr) * AS + ks * 8 + lc + 4];
            float a3 = Qs[(wm + lr + 8) * AS + ks * 8 + lc + 4];
            #pragma unroll
            for (int nf = 0; nf < 8; nf++) {
                float b0 = Ks[(nf * 8 + lr) * AS + ks * 8 + lc];
                float b1 = Ks[(nf * 8 + lr) * AS + ks * 8 + lc + 4];
                MMA_TF32(s[nf], a0, a1, a2, a3, b0, b1);
            }
        }

        if (k0 + 63 > q0 + wm) {
            int qi0 = q0 + wm + lr, qi1 = qi0 + 8;
            #pragma unroll
            for (int nf = 0; nf < 8; nf++) {
                int kj0 = k0 + nf * 8 + 2 * lc, kj1 = kj0 + 1;
                if (kj0 > qi0) s[nf][0] = -1e30f;
                if (kj1 > qi0) s[nf][1] = -1e30f;
                if (kj0 > qi1) s[nf][2] = -1e30f;
                if (kj1 > qi1) s[nf][3] = -1e30f;
            }
        }

        float mt0 = -1e30f, mt1 = -1e30f;
        #pragma unroll
        for (int nf = 0; nf < 8; nf++) {
            mt0 = fmaxf(mt0, fmaxf(s[nf][0], s[nf][1]));
            mt1 = fmaxf(mt1, fmaxf(s[nf][2], s[nf][3]));
        }
        mt0 = fmaxf(mt0, __shfl_xor_sync(0xffffffffu, mt0, 1));
        mt0 = fmaxf(mt0, __shfl_xor_sync(0xffffffffu, mt0, 2));
        mt1 = fmaxf(mt1, __shfl_xor_sync(0xffffffffu, mt1, 1));
        mt1 = fmaxf(mt1, __shfl_xor_sync(0xffffffffu, mt1, 2));
        float mn0 = fmaxf(m0v, mt0), mn1 = fmaxf(m1v, mt1);
        float scl0 = __expf(m0v - mn0), scl1 = __expf(m1v - mn1);
        m0v = mn0; m1v = mn1;
        float ls0 = 0.f, ls1 = 0.f;
        #pragma unroll
        for (int nf = 0; nf < 8; nf++) {
            float p0 = __expf(s[nf][0] - mn0);
            float p1 = __expf(s[nf][1] - mn0);
            float p2 = __expf(s[nf][2] - mn1);
            float p3 = __expf(s[nf][3] - mn1);
            s[nf][0] = p0; s[nf][1] = p1; s[nf][2] = p2; s[nf][3] = p3;
            ls0 += p0 + p1; ls1 += p2 + p3;
        }
        ls0 += __shfl_xor_sync(0xffffffffu, ls0, 1);
        ls0 += __shfl_xor_sync(0xffffffffu, ls0, 2);
        ls1 += __shfl_xor_sync(0xffffffffu, ls1, 1);
        ls1 += __shfl_xor_sync(0xffffffffu, ls1, 2);
        l0 = l0 * scl0 + ls0;
        l1 = l1 * scl1 + ls1;
        #pragma unroll
        for (int nf = 0; nf < 8; nf++) {
            o[nf][0] *= scl0; o[nf][1] *= scl0;
            o[nf][2] *= scl1; o[nf][3] *= scl1;
        }

        #pragma unroll
        for (int nf = 0; nf < 8; nf++) {
            Ps[(wm + lr) * AS + nf * 8 + 2 * lc]     = tf32r(s[nf][0]);
            Ps[(wm + lr) * AS + nf * 8 + 2 * lc + 1] = tf32r(s[nf][1]);
            Ps[(wm + lr + 8) * AS + nf * 8 + 2 * lc]     = tf32r(s[nf][2]);
            Ps[(wm + lr + 8) * AS + nf * 8 + 2 * lc + 1] = tf32r(s[nf][3]);
        }
        __syncwarp();

        #pragma unroll
        for (int ks = 0; ks < 8; ks++) {
            float a0 = Ps[(wm + lr) * AS + ks * 8 + lc];
            float a1 = Ps[(wm + lr + 8) * AS + ks * 8 + lc];
            float a2 = Ps[(wm + lr) * AS + ks * 8 + lc + 4];
            float a3 = Ps[(wm + lr + 8) * AS + ks * 8 + lc + 4];
            #pragma unroll
            for (int nf = 0; nf < 8; nf++) {
                float b0 = Vn[(ks * 8 + lc) * AS + nf * 8 + lr];
                float b1 = Vn[(ks * 8 + lc + 4) * AS + nf * 8 + lr];
                MMA_TF32(o[nf], a0, a1, a2, a3, b0, b1);
            }
        }
        __syncthreads();
    }

    // epilogue -> half head-concat layout
    float il0 = 1.0f / l0, il1 = 1.0f / l1;
    int row0 = q0 + wm + lr, row1 = row0 + 8;
    #pragma unroll
    for (int nf = 0; nf < 8; nf++) {
        int col = h * HD + nf * 8 + 2 * lc;
        *(__half2*)&g_attnh[(size_t)(b * SEQ + row0) * DM + col] =
            __floats2half2_rn(o[nf][0] * il0, o[nf][1] * il0);
        *(__half2*)&g_attnh[(size_t)(b * SEQ + row1) * DM + col] =
            __floats2half2_rn(o[nf][2] * il1, o[nf][3] * il1);
    }
}

// ---------------- launch ---------------------------------------------------
extern "C" void kernel_launch(void* const* d_in, const int* in_sizes, int n_in,
                              void* d_out, int out_size)
{
    (void)in_sizes; (void)n_in; (void)out_size;
    const float* x     = (const float*)d_in[0];
    const float* w_qkv = (const float*)d_in[1];
    const float* b_qkv = (const float*)d_in[2];
    const float* w_out = (const float*)d_in[3];
    const float* b_out = (const float*)d_in[4];
    const float* w_fc1 = (const float*)d_in[5];
    const float* b_fc1 = (const float*)d_in[6];
    const float* w_fc2 = (const float*)d_in[7];
    const float* b_fc2 = (const float*)d_in[8];
    const float* ln1s  = (const float*)d_in[9];
    const float* ln1b  = (const float*)d_in[10];
    const float* ln2s  = (const float*)d_in[11];
    const float* ln2b  = (const float*)d_in[12];
    float* out = (float*)d_out;

    __half *xn, *attnh, *ff, *wqkvT, *woutT, *wfc1T, *wfc2T;
    float *qkv, *res1;
    cudaGetSymbolAddress((void**)&xn,    g_xn);
    cudaGetSymbolAddress((void**)&qkv,   g_qkv);
    cudaGetSymbolAddress((void**)&attnh, g_attnh);
    cudaGetSymbolAddress((void**)&res1,  g_res1);
    cudaGetSymbolAddress((void**)&ff,    g_ff);
    cudaGetSymbolAddress((void**)&wqkvT, g_wqkvT);
    cudaGetSymbolAddress((void**)&woutT, g_woutT);
    cudaGetSymbolAddress((void**)&wfc1T, g_wfc1T);
    cudaGetSymbolAddress((void**)&wfc2T, g_wfc2T);

    cudaFuncSetAttribute(gemm_f16,
        cudaFuncAttributeMaxDynamicSharedMemorySize, HGSM);
    cudaFuncSetAttribute(attn_mma,
        cudaFuncAttributeMaxDynamicSharedMemorySize, ATTN_SM_BYTES);

    // 0. weight transposes (half, K-contiguous)
    transpose_h<<<dim3(3 * DM / 32, DM / 32), 256>>>(w_qkv, wqkvT, DM, 3 * DM);
    transpose_h<<<dim3(DM / 32, DM / 32), 256>>>(w_out, woutT, DM, DM);
    transpose_h<<<dim3(DFF / 32, DM / 32), 256>>>(w_fc1, wfc1T, DM, DFF);
    transpose_h<<<dim3(DM / 32, DFF / 32), 256>>>(w_fc2, wfc2T, DFF, DM);

    // 1. LN1 -> half
    ln_kernel<<<NROWS, 256>>>(x, ln1s, ln1b, xn);
    // 2. QKV projection -> fp32
    gemm_f16<<<dim3(3 * DM / 128, NROWS / 128), 256, HGSM>>>(
        xn, wqkvT, b_qkv, (const float*)0, qkv, (__half*)0,
        NROWS, 3 * DM, DM, 0);
    // 3. causal flash attention -> half
    attn_mma<<<dim3(SEQ / 128, BATCH * NHEAD), 256, ATTN_SM_BYTES>>>();
    // 4. out projection + residual(x) -> fp32
    gemm_f16<<<dim3(DM / 128, NROWS / 128), 256, HGSM>>>(
        attnh, woutT, b_out, x, res1, (__half*)0, NROWS, DM, DM, 1);
    // 5. LN2 -> half
    ln_kernel<<<NROWS, 256>>>(res1, ln2s, ln2b, xn);
    // 6. FC1 + gelu -> half
    gemm_f16<<<dim3(DFF / 128, NROWS / 128), 256, HGSM>>>(
        xn, wfc1T, b_fc1, (const float*)0, (float*)0, ff, NROWS, DFF, DM, 2);
    // 7. FC2 + residual(res1) -> fp32 out
    gemm_f16<<<dim3(DM / 128, NROWS / 128), 256, HGSM>>>(
        ff, wfc2T, b_fc2, res1, out, (__half*)0, NROWS, DM, DFF, 1);
}

// round 12
// speedup vs baseline: 5.8131x; 1.2506x over previous
#include <cuda_runtime.h>
#include <cuda_fp16.h>
#include <math.h>
#include <stdint.h>

#define BATCH 4
#define SEQ   2048
#define DM    1024
#define DFF   4096
#define NHEAD 16
#define HD    64
#define NROWS (BATCH*SEQ)   /* 8192 */

// ---------------- scratch (device globals; no allocation allowed) ----------
__device__ __half g_xn   [(size_t)NROWS * DM];        // LN out (half)
__device__ __half g_qkvh [(size_t)NROWS * 3 * DM];    // qkv (half)
__device__ __half g_attnh[(size_t)NROWS * DM];        // attention out (half)
__device__ float  g_res1 [(size_t)NROWS * DM];
__device__ __half g_ff   [(size_t)NROWS * DFF];       // gelu out (half)
// transposed (N-major, K-contig) half weights
__device__ __half g_wqkvT[(size_t)3 * DM * DM];
__device__ __half g_woutT[(size_t)DM * DM];
__device__ __half g_wfc1T[(size_t)DFF * DM];
__device__ __half g_wfc2T[(size_t)DM * DFF];

// ---------------- helpers ---------------------------------------------------
__device__ __forceinline__ void cpa16(uint32_t dst, const void* src) {
    asm volatile("cp.async.cg.shared.global [%0], [%1], 16;" :: "r"(dst), "l"(src));
}
#define CP_COMMIT() asm volatile("cp.async.commit_group;" ::: "memory")
#define CP_WAIT(n)  asm volatile("cp.async.wait_group %0;" :: "n"(n) : "memory")

__device__ __forceinline__ uint32_t smem_u32(const void* p) {
    uint32_t a;
    asm("{ .reg .u64 t; cvta.to.shared.u64 t, %1; cvt.u32.u64 %0, t; }" : "=r"(a) : "l"(p));
    return a;
}
__device__ __forceinline__ float gelu_f(float x) {
    float x3 = x * x * x;
    return 0.5f * x * (1.0f + tanhf(0.7978845608028654f * (x + 0.044715f * x3)));
}

#define LDSM4(r0, r1, r2, r3, addr) \
    asm volatile("ldmatrix.sync.aligned.m8n8.x4.shared.b16 {%0,%1,%2,%3}, [%4];" \
        : "=r"(r0), "=r"(r1), "=r"(r2), "=r"(r3) : "r"(addr))
#define LDSM4T(r0, r1, r2, r3, addr) \
    asm volatile("ldmatrix.sync.aligned.m8n8.x4.trans.shared.b16 {%0,%1,%2,%3}, [%4];" \
        : "=r"(r0), "=r"(r1), "=r"(r2), "=r"(r3) : "r"(addr))

#define MMA_F16(c, a0,a1,a2,a3, b0,b1)                                      \
    asm volatile(                                                           \
        "mma.sync.aligned.m16n8k16.row.col.f32.f16.f16.f32 "                \
        "{%0,%1,%2,%3}, {%4,%5,%6,%7}, {%8,%9}, {%0,%1,%2,%3};\n"           \
        : "+f"((c)[0]), "+f"((c)[1]), "+f"((c)[2]), "+f"((c)[3])            \
        : "r"(a0), "r"(a1), "r"(a2), "r"(a3), "r"(b0), "r"(b1))

// ---------------- weight transpose -> half, K-contiguous --------------------
__global__ __launch_bounds__(256) void transpose_h(
    const float* __restrict__ in, __half* __restrict__ out, int K, int N)
{
    __shared__ float s[32 * 33];
    int t = threadIdx.x;
    int n0 = blockIdx.x * 32, k0 = blockIdx.y * 32;
    int r = t >> 3, c = (t & 7) * 4;
    float4 v = *(const float4*)(in + (size_t)(k0 + r) * N + n0 + c);
    s[(c + 0) * 33 + r] = v.x;
    s[(c + 1) * 33 + r] = v.y;
    s[(c + 2) * 33 + r] = v.z;
    s[(c + 3) * 33 + r] = v.w;
    __syncthreads();
    __half2 h0 = __floats2half2_rn(s[r * 33 + c + 0], s[r * 33 + c + 1]);
    __half2 h1 = __floats2half2_rn(s[r * 33 + c + 2], s[r * 33 + c + 3]);
    __half* op = out + (size_t)(n0 + r) * K + k0 + c;
    *(__half2*)(op)     = h0;
    *(__half2*)(op + 2) = h1;
}

// ---------------- LayerNorm (outputs half) ----------------------------------
__global__ __launch_bounds__(256) void ln_kernel(
    const float* __restrict__ x, const float* __restrict__ scale,
    const float* __restrict__ bias, __half* __restrict__ out)
{
    int row = blockIdx.x;
    const float4* xr = (const float4*)(x + (size_t)row * DM);
    float4 v = xr[threadIdx.x];
    float s  = v.x + v.y + v.z + v.w;
    float ss = v.x*v.x + v.y*v.y + v.z*v.z + v.w*v.w;
    #pragma unroll
    for (int o = 16; o > 0; o >>= 1) {
        s  += __shfl_xor_sync(0xffffffffu, s,  o);
        ss += __shfl_xor_sync(0xffffffffu, ss, o);
    }
    __shared__ float smS[8], smSS[8];
    __shared__ float sMean, sRstd;
    int w = threadIdx.x >> 5, lane = threadIdx.x & 31;
    if (lane == 0) { smS[w] = s; smSS[w] = ss; }
    __syncthreads();
    if (threadIdx.x == 0) {
        float S = 0.f, SS = 0.f;
        #pragma unroll
        for (int i = 0; i < 8; i++) { S += smS[i]; SS += smSS[i]; }
        float mean = S * (1.0f / DM);
        float var  = SS * (1.0f / DM) - mean * mean;
        sMean = mean; sRstd = rsqrtf(var + 1e-6f);
    }
    __syncthreads();
    float mean = sMean, rstd = sRstd;
    int c = threadIdx.x * 4;
    float4 sc = *(const float4*)(scale + c);
    float4 bi = *(const float4*)(bias  + c);
    __half2 h0 = __floats2half2_rn((v.x - mean) * rstd * sc.x + bi.x,
                                   (v.y - mean) * rstd * sc.y + bi.y);
    __half2 h1 = __floats2half2_rn((v.z - mean) * rstd * sc.z + bi.z,
                                   (v.w - mean) * rstd * sc.w + bi.w);
    __half* op = out + (size_t)row * DM + c;
    *(__half2*)(op)     = h0;
    *(__half2*)(op + 2) = h1;
}

// ---------------- FP16 mma.sync GEMM with ldmatrix + cp.async ---------------
// epi: 0 = bias -> half, 1 = bias + residual -> fp32, 2 = gelu(bias) -> half
#define HROWB 80
#define HSTGB (128 * HROWB * 2)
#define HGSM  (3 * HSTGB)

__global__ __launch_bounds__(256, 2) void gemm_f16(
    const __half* __restrict__ A, const __half* __restrict__ Bt,
    const float* __restrict__ bias, const float* __restrict__ R,
    float* __restrict__ C, __half* __restrict__ Ch,
    int M, int N, int K, int epi)
{
    extern __shared__ char smc[];
    const uint32_t sb = smem_u32(smc);

    const int t  = threadIdx.x;
    const int m0 = blockIdx.y * 128, n0 = blockIdx.x * 128;
    const int w  = t >> 5, lane = t & 31;
    const int wr = w >> 2, wc = w & 3;
    const int wm = wr * 64, wn = wc * 32;
    const int lr = lane >> 2, lc = lane & 3;

    float c[4][4][4];
    #pragma unroll
    for (int mf = 0; mf < 4; mf++)
        #pragma unroll
        for (int nf = 0; nf < 4; nf++)
            #pragma unroll
            for (int i = 0; i < 4; i++) c[mf][nf][i] = 0.f;

    const int row = t >> 2, kg = t & 3;
    const __half* Ap0 = A  + (size_t)(m0 + row)      * K + kg * 8;
    const __half* Ap1 = A  + (size_t)(m0 + 64 + row) * K + kg * 8;
    const __half* Bp0 = Bt + (size_t)(n0 + row)      * K + kg * 8;
    const __half* Bp1 = Bt + (size_t)(n0 + 64 + row) * K + kg * 8;
    const uint32_t dA0 = sb + row * HROWB + kg * 16;
    const uint32_t dA1 = sb + (row + 64) * HROWB + kg * 16;
    const uint32_t dB0 = sb + 10240 + row * HROWB + kg * 16;
    const uint32_t dB1 = sb + 10240 + (row + 64) * HROWB + kg * 16;

    const int NC = K >> 5;

    #define LOAD_STAGE(st, cc) do {                                   \
        uint32_t so_ = (uint32_t)(st) * HSTGB;                        \
        size_t ko_ = (size_t)(cc) << 5;                               \
        cpa16(dA0 + so_, Ap0 + ko_);                                  \
        cpa16(dA1 + so_, Ap1 + ko_);                                  \
        cpa16(dB0 + so_, Bp0 + ko_);                                  \
        cpa16(dB1 + so_, Bp1 + ko_);                                  \
        CP_COMMIT();                                                  \
    } while (0)

    LOAD_STAGE(0, 0);
    LOAD_STAGE(1, 1);

    const int lm_r = lane & 15;
    const int lm_k = (lane >> 4) * 16;

    int st = 0;
    for (int cc = 0; cc < NC; cc++) {
        CP_WAIT(1);
        __syncthreads();

        const uint32_t as = sb + st * HSTGB;
        const uint32_t bs = as + 10240;
        #pragma unroll
        for (int ks = 0; ks < 2; ks++) {
            uint32_t af[4][4];
            #pragma unroll
            for (int mf = 0; mf < 4; mf++) {
                uint32_t addr = as + (wm + mf * 16 + lm_r) * HROWB + ks * 32 + lm_k;
                LDSM4(af[mf][0], af[mf][1], af[mf][2], af[mf][3], addr);
            }
            uint32_t bf[4][2];
            #pragma unroll
            for (int np = 0; np < 2; np++) {
                uint32_t r0, r1, r2, r3;
                uint32_t addr = bs + (wn + np * 16 + lm_r) * HROWB + ks * 32 + lm_k;
                LDSM4(r0, r1, r2, r3, addr);
                bf[np * 2 + 0][0] = r0; bf[np * 2 + 0][1] = r2;
                bf[np * 2 + 1][0] = r1; bf[np * 2 + 1][1] = r3;
            }
            #pragma unroll
            for (int mf = 0; mf < 4; mf++)
                #pragma unroll
                for (int nf = 0; nf < 4; nf++)
                    MMA_F16(c[mf][nf], af[mf][0], af[mf][1], af[mf][2], af[mf][3],
                            bf[nf][0], bf[nf][1]);
        }
        __syncthreads();
        if (cc + 2 < NC) LOAD_STAGE((st + 2) % 3, cc + 2);
        else             CP_COMMIT();
        st = (st + 1) % 3;
    }
    #undef LOAD_STAGE

    #pragma unroll
    for (int mf = 0; mf < 4; mf++) {
        #pragma unroll
        for (int nf = 0; nf < 4; nf++) {
            int rowg = m0 + wm + mf * 16 + lr;
            int col  = n0 + wn + nf * 8 + lc * 2;
            float b0 = bias[col], b1 = bias[col + 1];
            float v0 = c[mf][nf][0] + b0;
            float v1 = c[mf][nf][1] + b1;
            float v2 = c[mf][nf][2] + b0;
            float v3 = c[mf][nf][3] + b1;
            if (epi == 1) {
                const float* r0 = R + (size_t)rowg * N + col;
                const float* r1 = R + (size_t)(rowg + 8) * N + col;
                v0 += r0[0]; v1 += r0[1];
                v2 += r1[0]; v3 += r1[1];
                *(float2*)(C + (size_t)rowg * N + col)       = make_float2(v0, v1);
                *(float2*)(C + (size_t)(rowg + 8) * N + col) = make_float2(v2, v3);
            } else if (epi == 2) {
                *(__half2*)(Ch + (size_t)rowg * N + col) =
                    __floats2half2_rn(gelu_f(v0), gelu_f(v1));
                *(__half2*)(Ch + (size_t)(rowg + 8) * N + col) =
                    __floats2half2_rn(gelu_f(v2), gelu_f(v3));
            } else {
                *(__half2*)(Ch + (size_t)rowg * N + col) =
                    __floats2half2_rn(v0, v1);
                *(__half2*)(Ch + (size_t)(rowg + 8) * N + col) =
                    __floats2half2_rn(v2, v3);
            }
        }
    }
}

// ---------------- Flash-attention, fp16 mma + ldmatrix (causal) -------------
// BQ=128, BK=64, 8 warps (16 q-rows each).  grid (SEQ/128, BATCH*NHEAD).
#define AH 72   /* halves per smem row (144 B): conflict-free ldmatrix */
#define ATTN_SM_BYTES ((128*AH + 64*AH + 64*AH + 128*AH) * 2)  /* 55296 */

__global__ __launch_bounds__(256) void attn_f16()
{
    extern __shared__ __half smh[];
    __half* Qs = smh;                 // [128][AH]
    __half* Ks = Qs + 128 * AH;       // [64][AH]
    __half* Vs = Ks + 64 * AH;        // [64][AH] natural [k][d]
    __half* Ps = Vs + 64 * AH;        // [128][AH] per-warp slices
    const uint32_t sQ = smem_u32(Qs), sK = smem_u32(Ks),
                   sV = smem_u32(Vs), sP = smem_u32(Ps);

    const int t = threadIdx.x, w = t >> 5, lane = t & 31;
    const int lr = lane >> 2, lc = lane & 3;
    const int lm_r = lane & 15, lm_c = (lane >> 4) * 8;   // ldmatrix halves
    const int qt = blockIdx.x, bh = blockIdx.y;
    const int b = bh >> 4, h = bh & 15;
    const size_t baseBH = (size_t)b * SEQ * (3 * DM) + (size_t)h * HD;
    const int q0 = qt * 128;
    const int wm = w * 16;

    // load Q (scaled by 0.125 — exact in fp16)
    const __half2 hscale = __floats2half2_rn(0.125f, 0.125f);
    for (int i = t; i < 128 * 8; i += 256) {
        int r = i >> 3, g = i & 7;
        uint4 v = *(const uint4*)&g_qkvh[baseBH + (size_t)(q0 + r) * (3 * DM) + g * 8];
        __half2* hp = (__half2*)&v;
        hp[0] = __hmul2(hp[0], hscale);
        hp[1] = __hmul2(hp[1], hscale);
        hp[2] = __hmul2(hp[2], hscale);
        hp[3] = __hmul2(hp[3], hscale);
        *(uint4*)&Qs[r * AH + g * 8] = v;
    }

    float o[8][4];
    #pragma unroll
    for (int nf = 0; nf < 8; nf++)
        #pragma unroll
        for (int i = 0; i < 4; i++) o[nf][i] = 0.f;
    float m0v = -1e30f, m1v = -1e30f, l0 = 0.f, l1 = 0.f;

    const int ntile = (q0 + 128) / 64;
    for (int kt = 0; kt < ntile; kt++) {
        int k0 = kt * 64;
        for (int i = t; i < 64 * 8; i += 256) {
            int r = i >> 3, g = i & 7;
            size_t base = baseBH + (size_t)(k0 + r) * (3 * DM);
            *(uint4*)&Ks[r * AH + g * 8] = *(const uint4*)&g_qkvh[base + DM + g * 8];
            *(uint4*)&Vs[r * AH + g * 8] = *(const uint4*)&g_qkvh[base + 2 * DM + g * 8];
        }
        __syncthreads();

        // ---- S = Q @ K^T : A=Q rows, B=K natural [n=kseq][k=d] ----
        float s[8][4];
        #pragma unroll
        for (int nf = 0; nf < 8; nf++)
            #pragma unroll
            for (int i = 0; i < 4; i++) s[nf][i] = 0.f;
        #pragma unroll
        for (int ks = 0; ks < 4; ks++) {          // d in steps of 16
            uint32_t a0, a1, a2, a3;
            LDSM4(a0, a1, a2, a3,
                  sQ + ((wm + lm_r) * AH + ks * 16 + lm_c) * 2);
            #pragma unroll
            for (int np = 0; np < 4; np++) {      // kseq in steps of 16
                uint32_t r0, r1, r2, r3;
                LDSM4(r0, r1, r2, r3,
                      sK + ((np * 16 + lm_r) * AH + ks * 16 + lm_c) * 2);
                MMA_F16(s[np * 2 + 0], a0, a1, a2, a3, r0, r2);
                MMA_F16(s[np * 2 + 1], a0, a1, a2, a3, r1, r3);
            }
        }

        // ---- causal mask ----
        if (k0 + 63 > q0 + wm) {
            int qi0 = q0 + wm + lr, qi1 = qi0 + 8;
            #pragma unroll
            for (int nf = 0; nf < 8; nf++) {
                int kj0 = k0 + nf * 8 + 2 * lc, kj1 = kj0 + 1;
                if (kj0 > qi0) s[nf][0] = -1e30f;
                if (kj1 > qi0) s[nf][1] = -1e30f;
                if (kj0 > qi1) s[nf][2] = -1e30f;
                if (kj1 > qi1) s[nf][3] = -1e30f;
            }
        }

        // ---- online softmax in registers ----
        float mt0 = -1e30f, mt1 = -1e30f;
        #pragma unroll
        for (int nf = 0; nf < 8; nf++) {
            mt0 = fmaxf(mt0, fmaxf(s[nf][0], s[nf][1]));
            mt1 = fmaxf(mt1, fmaxf(s[nf][2], s[nf][3]));
        }
        mt0 = fmaxf(mt0, __shfl_xor_sync(0xffffffffu, mt0, 1));
        mt0 = fmaxf(mt0, __shfl_xor_sync(0xffffffffu, mt0, 2));
        mt1 = fmaxf(mt1, __shfl_xor_sync(0xffffffffu, mt1, 1));
        mt1 = fmaxf(mt1, __shfl_xor_sync(0xffffffffu, mt1, 2));
        float mn0 = fmaxf(m0v, mt0), mn1 = fmaxf(m1v, mt1);
        float scl0 = __expf(m0v - mn0), scl1 = __expf(m1v - mn1);
        m0v = mn0; m1v = mn1;
        float ls0 = 0.f, ls1 = 0.f;
        #pragma unroll
        for (int nf = 0; nf < 8; nf++) {
            float p0 = __expf(s[nf][0] - mn0);
            float p1 = __expf(s[nf][1] - mn0);
            float p2 = __expf(s[nf][2] - mn1);
            float p3 = __expf(s[nf][3] - mn1);
            s[nf][0] = p0; s[nf][1] = p1; s[nf][2] = p2; s[nf][3] = p3;
            ls0 += p0 + p1; ls1 += p2 + p3;
        }
        ls0 += __shfl_xor_sync(0xffffffffu, ls0, 1);
        ls0 += __shfl_xor_sync(0xffffffffu, ls0, 2);
        ls1 += __shfl_xor_sync(0xffffffffu, ls1, 1);
        ls1 += __shfl_xor_sync(0xffffffffu, ls1, 2);
        l0 = l0 * scl0 + ls0;
        l1 = l1 * scl1 + ls1;
        #pragma unroll
        for (int nf = 0; nf < 8; nf++) {
            o[nf][0] *= scl0; o[nf][1] *= scl0;
            o[nf][2] *= scl1; o[nf][3] *= scl1;
        }

        // ---- P (half) -> per-warp smem slice ----
        #pragma unroll
        for (int nf = 0; nf < 8; nf++) {
            *(__half2*)&Ps[(wm + lr) * AH + nf * 8 + 2 * lc] =
                __floats2half2_rn(s[nf][0], s[nf][1]);
            *(__half2*)&Ps[(wm + lr + 8) * AH + nf * 8 + 2 * lc] =
                __floats2half2_rn(s[nf][2], s[nf][3]);
        }
        __syncwarp();

        // ---- O += P @ V : A=P rows, B=V via ldmatrix.trans ----
        #pragma unroll
        for (int ks = 0; ks < 4; ks++) {          // kseq in steps of 16
            uint32_t a0, a1, a2, a3;
            LDSM4(a0, a1, a2, a3,
                  sP + ((wm + lm_r) * AH + ks * 16 + lm_c) * 2);
            #pragma unroll
            for (int dp = 0; dp < 4; dp++) {      // d in steps of 16
                uint32_t r0, r1, r2, r3;
                LDSM4T(r0, r1, r2, r3,
                       sV + ((ks * 16 + lm_r) * AH + dp * 16 + lm_c) * 2);
                MMA_F16(o[dp * 2 + 0], a0, a1, a2, a3, r0, r1);
                MMA_F16(o[dp * 2 + 1], a0, a1, a2, a3, r2, r3);
            }
        }
        __syncthreads();
    }

    // ---- epilogue: O / l -> half head-concat layout ----
    float il0 = 1.0f / l0, il1 = 1.0f / l1;
    int row0 = q0 + wm + lr, row1 = row0 + 8;
    #pragma unroll
    for (int nf = 0; nf < 8; nf++) {
        int col = h * HD + nf * 8 + 2 * lc;
        *(__half2*)&g_attnh[(size_t)(b * SEQ + row0) * DM + col] =
            __floats2half2_rn(o[nf][0] * il0, o[nf][1] * il0);
        *(__half2*)&g_attnh[(size_t)(b * SEQ + row1) * DM + col] =
            __floats2half2_rn(o[nf][2] * il1, o[nf][3] * il1);
    }
}

// ---------------- launch ---------------------------------------------------
extern "C" void kernel_launch(void* const* d_in, const int* in_sizes, int n_in,
                              void* d_out, int out_size)
{
    (void)in_sizes; (void)n_in; (void)out_size;
    const float* x     = (const float*)d_in[0];
    const float* w_qkv = (const float*)d_in[1];
    const float* b_qkv = (const float*)d_in[2];
    const float* w_out = (const float*)d_in[3];
    const float* b_out = (const float*)d_in[4];
    const float* w_fc1 = (const float*)d_in[5];
    const float* b_fc1 = (const float*)d_in[6];
    const float* w_fc2 = (const float*)d_in[7];
    const float* b_fc2 = (const float*)d_in[8];
    const float* ln1s  = (const float*)d_in[9];
    const float* ln1b  = (const float*)d_in[10];
    const float* ln2s  = (const float*)d_in[11];
    const float* ln2b  = (const float*)d_in[12];
    float* out = (float*)d_out;

    __half *xn, *qkvh, *attnh, *ff, *wqkvT, *woutT, *wfc1T, *wfc2T;
    float *res1;
    cudaGetSymbolAddress((void**)&xn,    g_xn);
    cudaGetSymbolAddress((void**)&qkvh,  g_qkvh);
    cudaGetSymbolAddress((void**)&attnh, g_attnh);
    cudaGetSymbolAddress((void**)&res1,  g_res1);
    cudaGetSymbolAddress((void**)&ff,    g_ff);
    cudaGetSymbolAddress((void**)&wqkvT, g_wqkvT);
    cudaGetSymbolAddress((void**)&woutT, g_woutT);
    cudaGetSymbolAddress((void**)&wfc1T, g_wfc1T);
    cudaGetSymbolAddress((void**)&wfc2T, g_wfc2T);

    cudaFuncSetAttribute(gemm_f16,
        cudaFuncAttributeMaxDynamicSharedMemorySize, HGSM);
    cudaFuncSetAttribute(attn_f16,
        cudaFuncAttributeMaxDynamicSharedMemorySize, ATTN_SM_BYTES);

    // 0. weight transposes (half, K-contiguous)
    transpose_h<<<dim3(3 * DM / 32, DM / 32), 256>>>(w_qkv, wqkvT, DM, 3 * DM);
    transpose_h<<<dim3(DM / 32, DM / 32), 256>>>(w_out, woutT, DM, DM);
    transpose_h<<<dim3(DFF / 32, DM / 32), 256>>>(w_fc1, wfc1T, DM, DFF);
    transpose_h<<<dim3(DM / 32, DFF / 32), 256>>>(w_fc2, wfc2T, DFF, DM);

    // 1. LN1 -> half
    ln_kernel<<<NROWS, 256>>>(x, ln1s, ln1b, xn);
    // 2. QKV projection -> half
    gemm_f16<<<dim3(3 * DM / 128, NROWS / 128), 256, HGSM>>>(
        xn, wqkvT, b_qkv, (const float*)0, (float*)0, qkvh,
        NROWS, 3 * DM, DM, 0);
    // 3. causal flash attention (fp16 mma) -> half
    attn_f16<<<dim3(SEQ / 128, BATCH * NHEAD), 256, ATTN_SM_BYTES>>>();
    // 4. out projection + residual(x) -> fp32
    gemm_f16<<<dim3(DM / 128, NROWS / 128), 256, HGSM>>>(
        attnh, woutT, b_out, x, res1, (__half*)0, NROWS, DM, DM, 1);
    // 5. LN2 -> half
    ln_kernel<<<NROWS, 256>>>(res1, ln2s, ln2b, xn);
    // 6. FC1 + gelu -> half
    gemm_f16<<<dim3(DFF / 128, NROWS / 128), 256, HGSM>>>(
        xn, wfc1T, b_fc1, (const float*)0, (float*)0, ff, NROWS, DFF, DM, 2);
    // 7. FC2 + residual(res1) -> fp32 out
    gemm_f16<<<dim3(DM / 128, NROWS / 128), 256, HGSM>>>(
        ff, wfc2T, b_fc2, res1, out, (__half*)0, NROWS, DM, DFF, 1);
}